// round 2
// baseline (speedup 1.0000x reference)
#include <cuda_runtime.h>
#include <cstdint>

#define Hh   8
#define Bb   16
#define Gg   512
#define NQq  512
#define Dd   512
#define KDd  64
#define Ee   512
#define NCOL 6144           /* 12 * 512 */
#define ROWSM 8192          /* B * NQ   */
#define NORMS 0.125f

// ---------------- device scratch (static: allocation-guard safe) ----------
__device__ float g_Wcat[Dd * NCOL];                 // [d][col], col = w*512+h*64+k
__device__ float g_P[(size_t)ROWSM * NCOL];         // projections, 201 MB
__device__ float g_attT[(size_t)Bb * NQq * Gg];     // transposed att mask
__device__ float g_Hd[(size_t)ROWSM * (Hh * KDd)];  // attention heads (B,NQ,H,VD)

struct WPtrs { const float* w[12]; };

// ---------------- weight repack: 12 x (H,D,64) -> [D][6144] ---------------
__global__ void repack_kernel(WPtrs wp) {
    int idx = blockIdx.x * blockDim.x + threadIdx.x;
    if (idx >= Dd * NCOL) return;
    int d   = idx / NCOL;
    int col = idx - d * NCOL;
    int w   = col >> 9;          // which weight tensor
    int hk  = col & 511;
    int h   = hk >> 6;
    int k   = hk & 63;
    g_Wcat[idx] = wp.w[w][((size_t)h * Dd + d) * KDd + k];
}

// ---------------- att mask transpose: (B,G,NQ) -> (B,NQ,G) ----------------
__global__ void mask_transpose_kernel(const float* __restrict__ att) {
    __shared__ float t[32][33];
    int b  = blockIdx.z;
    int n0 = blockIdx.x * 32;
    int g0 = blockIdx.y * 32;
    const float* src = att + (size_t)b * Gg * NQq;
    t[threadIdx.y][threadIdx.x] = src[(size_t)(g0 + threadIdx.y) * NQq + n0 + threadIdx.x];
    __syncthreads();
    g_attT[(size_t)b * NQq * Gg + (size_t)(n0 + threadIdx.y) * Gg + g0 + threadIdx.x] =
        t[threadIdx.x][threadIdx.y];
}

// ---------------- fp32 SGEMM: C[M,N] = A[M,K] * B[K,N], row-major ---------
// BM=BN=128, BK=16, 256 threads, 8x8 microtile.
__global__ __launch_bounds__(256) void sgemm_kernel(
    const float* __restrict__ A, const float* __restrict__ Bm,
    float* __restrict__ C, int M, int N, int K) {
    __shared__ float As[16][128];
    __shared__ float Bs[16][132];
    int bx = blockIdx.x, by = blockIdx.y;
    int tid = threadIdx.x;
    int ty = tid >> 4, tx = tid & 15;

    const float* Aptr = A + (size_t)by * 128 * K;
    const float* Bptr = Bm + (size_t)bx * 128;

    float acc[8][8];
#pragma unroll
    for (int i = 0; i < 8; i++)
#pragma unroll
        for (int j = 0; j < 8; j++) acc[i][j] = 0.f;

    for (int k0 = 0; k0 < K; k0 += 16) {
#pragma unroll
        for (int l = 0; l < 2; l++) {
            int i  = tid + l * 256;
            int r  = i >> 2;
            int c4 = (i & 3) << 2;
            float4 v = *(const float4*)(Aptr + (size_t)r * K + k0 + c4);
            As[c4 + 0][r] = v.x; As[c4 + 1][r] = v.y;
            As[c4 + 2][r] = v.z; As[c4 + 3][r] = v.w;
            int r2  = i >> 5;
            int c42 = (i & 31) << 2;
            float4 w = *(const float4*)(Bptr + (size_t)(k0 + r2) * N + c42);
            *(float4*)(&Bs[r2][c42]) = w;
        }
        __syncthreads();
#pragma unroll
        for (int kk = 0; kk < 16; kk++) {
            float4 a0 = *(const float4*)(&As[kk][ty * 8]);
            float4 a1 = *(const float4*)(&As[kk][ty * 8 + 4]);
            float4 b0 = *(const float4*)(&Bs[kk][tx * 8]);
            float4 b1 = *(const float4*)(&Bs[kk][tx * 8 + 4]);
            float av[8] = {a0.x, a0.y, a0.z, a0.w, a1.x, a1.y, a1.z, a1.w};
            float bv[8] = {b0.x, b0.y, b0.z, b0.w, b1.x, b1.y, b1.z, b1.w};
#pragma unroll
            for (int i = 0; i < 8; i++)
#pragma unroll
                for (int j = 0; j < 8; j++) acc[i][j] += av[i] * bv[j];
        }
        __syncthreads();
    }
    float* Cb = C + (size_t)(by * 128 + ty * 8) * N + bx * 128 + tx * 8;
#pragma unroll
    for (int i = 0; i < 8; i++) {
        float4 o0 = make_float4(acc[i][0], acc[i][1], acc[i][2], acc[i][3]);
        float4 o1 = make_float4(acc[i][4], acc[i][5], acc[i][6], acc[i][7]);
        *(float4*)(Cb + (size_t)i * N)     = o0;
        *(float4*)(Cb + (size_t)i * N + 4) = o1;
    }
}

// ---------------- fused attention (flash-style online softmax) ------------
// Block: 128 queries x one (h,b). Loops 4 branches x 8 key tiles of 64.
// Threads 256 = 16(ty: 8 queries each) x 16(tx: 4 keys / 4 v-dims each).
#define ATTN_SMEM_FLOATS (64 * 132 + 64 * 68 + 64 * 68 + 64 * 132)
#define ATTN_SMEM_BYTES  (ATTN_SMEM_FLOATS * 4)

__global__ __launch_bounds__(256) void attn_kernel(
    const float* __restrict__ attm,
    const float* __restrict__ gmk,
    const float* __restrict__ sd) {
    extern __shared__ float smbuf[];
    float* Qs = smbuf;                 // [k(64)][q(128)] pad 132
    float* Ks = Qs + 64 * 132;         // [k(64)][g(64)]  pad 68
    float* Vs = Ks + 64 * 68;          // [g(64)][v(64)]  pad 68
    float* Ps = Vs + 64 * 68;          // [g(64)][q(128)] pad 132

    int qt = blockIdx.x;               // 0..3
    int hb = blockIdx.y;               // 0..127
    int h  = hb >> 4;
    int b  = hb & 15;
    int tid = threadIdx.x;
    int ty = tid >> 4, tx = tid & 15;

    float m[8], den[8], acc[8][4];
#pragma unroll
    for (int i = 0; i < 8; i++) {
        m[i] = -1e30f; den[i] = 0.f;
#pragma unroll
        for (int j = 0; j < 4; j++) acc[i][j] = 0.f;
    }

    const size_t mboff = (size_t)b * NQq * Gg;
    const float* mbase[4] = { sd + mboff, g_attT + mboff, attm + mboff, gmk + mboff };

    for (int c = 0; c < 4; c++) {
        // load Q tile (128 x 64), transposed into Qs[k][q]
        const float* Qg = g_P + (size_t)(b * NQq + qt * 128) * NCOL + (3 * c) * 512 + h * 64;
#pragma unroll
        for (int l = 0; l < 8; l++) {
            int i  = tid + l * 256;
            int r  = i >> 4;
            int c4 = (i & 15) << 2;
            float4 v = *(const float4*)(Qg + (size_t)r * NCOL + c4);
            Qs[(c4 + 0) * 132 + r] = v.x;
            Qs[(c4 + 1) * 132 + r] = v.y;
            Qs[(c4 + 2) * 132 + r] = v.z;
            Qs[(c4 + 3) * 132 + r] = v.w;
        }
        const float* mb = mbase[c];

        for (int g0 = 0; g0 < Gg; g0 += 64) {
            __syncthreads();   // prior PV done (Ks/Vs/Ps free), Qs visible
            const float* Kg = g_P + (size_t)(b * NQq + g0) * NCOL + (3 * c + 1) * 512 + h * 64;
            const float* Vg = g_P + (size_t)(b * NQq + g0) * NCOL + (3 * c + 2) * 512 + h * 64;
#pragma unroll
            for (int l = 0; l < 4; l++) {
                int i  = tid + l * 256;
                int r  = i >> 4;
                int c4 = (i & 15) << 2;
                float4 kv = *(const float4*)(Kg + (size_t)r * NCOL + c4);
                Ks[(c4 + 0) * 68 + r] = kv.x;
                Ks[(c4 + 1) * 68 + r] = kv.y;
                Ks[(c4 + 2) * 68 + r] = kv.z;
                Ks[(c4 + 3) * 68 + r] = kv.w;
                float4 vv = *(const float4*)(Vg + (size_t)r * NCOL + c4);
                *(float4*)(Vs + r * 68 + c4) = vv;
            }
            __syncthreads();

            // S = Q K^T  (8q x 4g per thread)
            float s[8][4];
#pragma unroll
            for (int i = 0; i < 8; i++)
#pragma unroll
                for (int j = 0; j < 4; j++) s[i][j] = 0.f;
#pragma unroll 8
            for (int k = 0; k < 64; k++) {
                float4 a0 = *(const float4*)(Qs + k * 132 + ty * 8);
                float4 a1 = *(const float4*)(Qs + k * 132 + ty * 8 + 4);
                float4 bb = *(const float4*)(Ks + k * 68 + tx * 4);
                float av[8] = {a0.x, a0.y, a0.z, a0.w, a1.x, a1.y, a1.z, a1.w};
                float bv[4] = {bb.x, bb.y, bb.z, bb.w};
#pragma unroll
                for (int i = 0; i < 8; i++)
#pragma unroll
                    for (int j = 0; j < 4; j++) s[i][j] += av[i] * bv[j];
            }

            // masked online softmax update (row stats across 16-lane tx group)
#pragma unroll
            for (int i = 0; i < 8; i++) {
                int n = qt * 128 + ty * 8 + i;
                float4 mv = *(const float4*)(mb + (size_t)n * Gg + g0 + tx * 4);
                float mk[4] = {mv.x, mv.y, mv.z, mv.w};
#pragma unroll
                for (int j = 0; j < 4; j++)
                    s[i][j] = (mk[j] != 0.0f) ? s[i][j] * NORMS : -1e30f;
                float rm = fmaxf(fmaxf(s[i][0], s[i][1]), fmaxf(s[i][2], s[i][3]));
#pragma unroll
                for (int off = 8; off >= 1; off >>= 1)
                    rm = fmaxf(rm, __shfl_xor_sync(0xffffffffu, rm, off));
                float mn = fmaxf(m[i], rm);
                float sc = __expf(m[i] - mn);          // -1e30 - -1e30 -> exp(0)=1, acc==0 so safe
                float rs = 0.f;
#pragma unroll
                for (int j = 0; j < 4; j++) {
                    float p = (s[i][j] > -1e29f) ? __expf(s[i][j] - mn) : 0.f;
                    Ps[(tx * 4 + j) * 132 + ty * 8 + i] = p;
                    rs += p;
                }
#pragma unroll
                for (int off = 8; off >= 1; off >>= 1)
                    rs += __shfl_xor_sync(0xffffffffu, rs, off);
                den[i] = den[i] * sc + rs;
                m[i]   = mn;
#pragma unroll
                for (int j = 0; j < 4; j++) acc[i][j] *= sc;
            }
            __syncthreads();

            // O += P V   (8q x 4v per thread)
#pragma unroll 8
            for (int g = 0; g < 64; g++) {
                float4 p0 = *(const float4*)(Ps + g * 132 + ty * 8);
                float4 p1 = *(const float4*)(Ps + g * 132 + ty * 8 + 4);
                float4 vv = *(const float4*)(Vs + g * 68 + tx * 4);
                float pv[8] = {p0.x, p0.y, p0.z, p0.w, p1.x, p1.y, p1.z, p1.w};
                float vj[4] = {vv.x, vv.y, vv.z, vv.w};
#pragma unroll
                for (int i = 0; i < 8; i++)
#pragma unroll
                    for (int j = 0; j < 4; j++) acc[i][j] += pv[i] * vj[j];
            }
        }
        __syncthreads();  // all PV reads done before next c overwrites Qs tiles
    }

    // epilogue: normalize and write heads as (B,NQ,H,VD)
    size_t outbase = (size_t)(b * NQq + qt * 128 + ty * 8) * 512 + h * 64 + tx * 4;
#pragma unroll
    for (int i = 0; i < 8; i++) {
        float inv = (den[i] > 0.f) ? 1.f / den[i] : 0.f;
        float4 o = make_float4(acc[i][0] * inv, acc[i][1] * inv,
                               acc[i][2] * inv, acc[i][3] * inv);
        *(float4*)(g_Hd + outbase + (size_t)i * 512) = o;
    }
}

// ---------------- launch ---------------------------------------------------
extern "C" void kernel_launch(void* const* d_in, const int* in_sizes, int n_in,
                              void* d_out, int out_size) {
    const float* q    = (const float*)d_in[0];
    const float* attM = (const float*)d_in[1];
    const float* grpM = (const float*)d_in[2];
    const float* sdM  = (const float*)d_in[3];
    WPtrs wp;
    for (int i = 0; i < 12; i++) wp.w[i] = (const float*)d_in[4 + i];
    const float* wout = (const float*)d_in[16];
    float* out = (float*)d_out;

    void *pWcat, *pP, *pHd;
    cudaGetSymbolAddress(&pWcat, g_Wcat);
    cudaGetSymbolAddress(&pP, g_P);
    cudaGetSymbolAddress(&pHd, g_Hd);

    // 1. repack weights
    repack_kernel<<<(Dd * NCOL + 255) / 256, 256>>>(wp);
    // 2. transpose att mask
    mask_transpose_kernel<<<dim3(16, 16, 16), dim3(32, 32)>>>(attM);
    // 3. fused projection GEMM: [8192 x 512] * [512 x 6144]
    sgemm_kernel<<<dim3(NCOL / 128, ROWSM / 128), 256>>>(
        q, (const float*)pWcat, (float*)pP, ROWSM, NCOL, Dd);
    // 4. fused masked 4-branch attention
    cudaFuncSetAttribute(attn_kernel, cudaFuncAttributeMaxDynamicSharedMemorySize,
                         ATTN_SMEM_BYTES);
    attn_kernel<<<dim3(4, 128), 256, ATTN_SMEM_BYTES>>>(attM, grpM, sdM);
    // 5. output projection: [8192 x 512] * [512 x 512]
    sgemm_kernel<<<dim3(Ee / 128, ROWSM / 128), 256>>>(
        (const float*)pHd, wout, out, ROWSM, Ee, Dd);
}

// round 3
// speedup vs baseline: 1.0005x; 1.0005x over previous
#include <cuda_runtime.h>
#include <cstdint>

#define Hh   8
#define Bb   16
#define Gg   512
#define NQq  512
#define Dd   512
#define KDd  64
#define Ee   512
#define NCOL 6144           /* 12 * 512 */
#define ROWSM 8192          /* B * NQ   */
#define NORMS 0.125f

typedef unsigned long long u64;

// ---------------- packed fp32x2 helpers (sm_103a FFMA2 path) --------------
__device__ __forceinline__ u64 ffma2(u64 a, u64 b, u64 c) {
    u64 d;
    asm("fma.rn.f32x2 %0, %1, %2, %3;" : "=l"(d) : "l"(a), "l"(b), "l"(c));
    return d;
}
__device__ __forceinline__ u64 fmul2(u64 a, u64 b) {
    u64 d;
    asm("mul.rn.f32x2 %0, %1, %2;" : "=l"(d) : "l"(a), "l"(b));
    return d;
}
__device__ __forceinline__ u64 pack2(float lo, float hi) {
    u64 d;
    asm("mov.b64 %0, {%1, %2};" : "=l"(d) : "f"(lo), "f"(hi));
    return d;
}
__device__ __forceinline__ void unpack2(u64 v, float& lo, float& hi) {
    asm("mov.b64 {%0, %1}, %2;" : "=f"(lo), "=f"(hi) : "l"(v));
}
__device__ __forceinline__ u64 d2u(double v) { return __double_as_longlong(v); }

// ---------------- device scratch (static: allocation-guard safe) ----------
__device__ float g_Wcat[Dd * NCOL];                 // [d][col], col = w*512+h*64+k
__device__ float g_P[(size_t)ROWSM * NCOL];         // projections, 201 MB
__device__ float g_attT[(size_t)Bb * NQq * Gg];     // transposed att mask
__device__ float g_Hd[(size_t)ROWSM * (Hh * KDd)];  // attention heads (B,NQ,H,VD)

struct WPtrs { const float* w[12]; };

// ---------------- weight repack: 12 x (H,D,64) -> [D][6144] ---------------
__global__ void repack_kernel(WPtrs wp) {
    int idx = blockIdx.x * blockDim.x + threadIdx.x;
    if (idx >= Dd * NCOL) return;
    int d   = idx / NCOL;
    int col = idx - d * NCOL;
    int w   = col >> 9;          // which weight tensor
    int hk  = col & 511;
    int h   = hk >> 6;
    int k   = hk & 63;
    g_Wcat[idx] = wp.w[w][((size_t)h * Dd + d) * KDd + k];
}

// ---------------- att mask transpose: (B,G,NQ) -> (B,NQ,G) ----------------
__global__ void mask_transpose_kernel(const float* __restrict__ att) {
    __shared__ float t[32][33];
    int b  = blockIdx.z;
    int n0 = blockIdx.x * 32;
    int g0 = blockIdx.y * 32;
    const float* src = att + (size_t)b * Gg * NQq;
    t[threadIdx.y][threadIdx.x] = src[(size_t)(g0 + threadIdx.y) * NQq + n0 + threadIdx.x];
    __syncthreads();
    g_attT[(size_t)b * NQq * Gg + (size_t)(n0 + threadIdx.y) * Gg + g0 + threadIdx.x] =
        t[threadIdx.x][threadIdx.y];
}

// ---------------- fp32 SGEMM: C[M,N] = A[M,K] * B[K,N], row-major ---------
// BM=BN=128, BK=16, 256 threads, 8x8 microtile, FFMA2 inner loop.
__global__ __launch_bounds__(256) void sgemm_kernel(
    const float* __restrict__ A, const float* __restrict__ Bm,
    float* __restrict__ C, int M, int N, int K) {
    __shared__ float As[16][128];
    __shared__ float Bs[16][132];
    int bx = blockIdx.x, by = blockIdx.y;
    int tid = threadIdx.x;
    int ty = tid >> 4, tx = tid & 15;

    const float* Aptr = A + (size_t)by * 128 * K;
    const float* Bptr = Bm + (size_t)bx * 128;

    u64 acc2[8][4];   // acc2[i][jp] packs columns (2jp, 2jp+1) for row i
#pragma unroll
    for (int i = 0; i < 8; i++)
#pragma unroll
        for (int j = 0; j < 4; j++) acc2[i][j] = 0ULL;

    for (int k0 = 0; k0 < K; k0 += 16) {
#pragma unroll
        for (int l = 0; l < 2; l++) {
            int i  = tid + l * 256;
            int r  = i >> 2;
            int c4 = (i & 3) << 2;
            float4 v = *(const float4*)(Aptr + (size_t)r * K + k0 + c4);
            As[c4 + 0][r] = v.x; As[c4 + 1][r] = v.y;
            As[c4 + 2][r] = v.z; As[c4 + 3][r] = v.w;
            int r2  = i >> 5;
            int c42 = (i & 31) << 2;
            float4 w = *(const float4*)(Bptr + (size_t)(k0 + r2) * N + c42);
            *(float4*)(&Bs[r2][c42]) = w;
        }
        __syncthreads();
#pragma unroll
        for (int kk = 0; kk < 16; kk++) {
            float4 a0 = *(const float4*)(&As[kk][ty * 8]);
            float4 a1 = *(const float4*)(&As[kk][ty * 8 + 4]);
            // B pairs loaded directly as packed 64-bit (rows 16B-aligned: 528B stride)
            double2 b01 = *(const double2*)(&Bs[kk][tx * 8]);
            double2 b23 = *(const double2*)(&Bs[kk][tx * 8 + 4]);
            u64 bv2[4] = { d2u(b01.x), d2u(b01.y), d2u(b23.x), d2u(b23.y) };
            float av[8] = {a0.x, a0.y, a0.z, a0.w, a1.x, a1.y, a1.z, a1.w};
#pragma unroll
            for (int i = 0; i < 8; i++) {
                u64 aa = pack2(av[i], av[i]);
#pragma unroll
                for (int j = 0; j < 4; j++) acc2[i][j] = ffma2(aa, bv2[j], acc2[i][j]);
            }
        }
        __syncthreads();
    }
    float* Cb = C + (size_t)(by * 128 + ty * 8) * N + bx * 128 + tx * 8;
#pragma unroll
    for (int i = 0; i < 8; i++) {
        float o[8];
#pragma unroll
        for (int j = 0; j < 4; j++) unpack2(acc2[i][j], o[2 * j], o[2 * j + 1]);
        *(float4*)(Cb + (size_t)i * N)     = make_float4(o[0], o[1], o[2], o[3]);
        *(float4*)(Cb + (size_t)i * N + 4) = make_float4(o[4], o[5], o[6], o[7]);
    }
}

// ---------------- fused attention (flash-style online softmax) ------------
// Block: 128 queries x one (h,b). Loops 4 branches x 8 key tiles of 64.
// Threads 256 = 16(ty: 8 queries each) x 16(tx: 4 keys / 4 v-dims each).
#define ATTN_SMEM_FLOATS (64 * 132 + 64 * 68 + 64 * 68 + 64 * 132)
#define ATTN_SMEM_BYTES  (ATTN_SMEM_FLOATS * 4)

__global__ __launch_bounds__(256) void attn_kernel(
    const float* __restrict__ attm,
    const float* __restrict__ gmk,
    const float* __restrict__ sd) {
    extern __shared__ float smbuf[];
    float* Qs = smbuf;                 // [k(64)][q(128)] pad 132
    float* Ks = Qs + 64 * 132;         // [k(64)][g(64)]  pad 68
    float* Vs = Ks + 64 * 68;          // [g(64)][v(64)]  pad 68
    float* Ps = Vs + 64 * 68;          // [g(64)][q(128)] pad 132

    int qt = blockIdx.x;               // 0..3
    int hb = blockIdx.y;               // 0..127
    int h  = hb >> 4;
    int b  = hb & 15;
    int tid = threadIdx.x;
    int ty = tid >> 4, tx = tid & 15;

    float m[8], den[8];
    u64 o2[4][4];                      // o2[ip][j] packs rows (2ip, 2ip+1), col j
#pragma unroll
    for (int i = 0; i < 8; i++) { m[i] = -1e30f; den[i] = 0.f; }
#pragma unroll
    for (int ip = 0; ip < 4; ip++)
#pragma unroll
        for (int j = 0; j < 4; j++) o2[ip][j] = 0ULL;

    const size_t mboff = (size_t)b * NQq * Gg;
    const float* mbase[4] = { sd + mboff, g_attT + mboff, attm + mboff, gmk + mboff };

    for (int c = 0; c < 4; c++) {
        // load Q tile (128 x 64), transposed into Qs[k][q]
        const float* Qg = g_P + (size_t)(b * NQq + qt * 128) * NCOL + (3 * c) * 512 + h * 64;
#pragma unroll
        for (int l = 0; l < 8; l++) {
            int i  = tid + l * 256;
            int r  = i >> 4;
            int c4 = (i & 15) << 2;
            float4 v = *(const float4*)(Qg + (size_t)r * NCOL + c4);
            Qs[(c4 + 0) * 132 + r] = v.x;
            Qs[(c4 + 1) * 132 + r] = v.y;
            Qs[(c4 + 2) * 132 + r] = v.z;
            Qs[(c4 + 3) * 132 + r] = v.w;
        }
        const float* mb = mbase[c];

        for (int g0 = 0; g0 < Gg; g0 += 64) {
            __syncthreads();   // prior PV done (Ks/Vs/Ps free), Qs visible
            const float* Kg = g_P + (size_t)(b * NQq + g0) * NCOL + (3 * c + 1) * 512 + h * 64;
            const float* Vg = g_P + (size_t)(b * NQq + g0) * NCOL + (3 * c + 2) * 512 + h * 64;
#pragma unroll
            for (int l = 0; l < 4; l++) {
                int i  = tid + l * 256;
                int r  = i >> 4;
                int c4 = (i & 15) << 2;
                float4 kv = *(const float4*)(Kg + (size_t)r * NCOL + c4);
                Ks[(c4 + 0) * 68 + r] = kv.x;
                Ks[(c4 + 1) * 68 + r] = kv.y;
                Ks[(c4 + 2) * 68 + r] = kv.z;
                Ks[(c4 + 3) * 68 + r] = kv.w;
                float4 vv = *(const float4*)(Vg + (size_t)r * NCOL + c4);
                *(float4*)(Vs + r * 68 + c4) = vv;
            }
            __syncthreads();

            // S = Q K^T  (8q x 4g per thread), rows paired into f32x2
            u64 s2[4][4];
#pragma unroll
            for (int ip = 0; ip < 4; ip++)
#pragma unroll
                for (int j = 0; j < 4; j++) s2[ip][j] = 0ULL;
#pragma unroll 8
            for (int k = 0; k < 64; k++) {
                double2 ap0 = *(const double2*)(Qs + k * 132 + ty * 8);
                double2 ap1 = *(const double2*)(Qs + k * 132 + ty * 8 + 4);
                u64 av2[4] = { d2u(ap0.x), d2u(ap0.y), d2u(ap1.x), d2u(ap1.y) };
                float4 bb = *(const float4*)(Ks + k * 68 + tx * 4);
                float bv[4] = {bb.x, bb.y, bb.z, bb.w};
#pragma unroll
                for (int j = 0; j < 4; j++) {
                    u64 bc = pack2(bv[j], bv[j]);
#pragma unroll
                    for (int ip = 0; ip < 4; ip++)
                        s2[ip][j] = ffma2(av2[ip], bc, s2[ip][j]);
                }
            }
            float s[8][4];
#pragma unroll
            for (int ip = 0; ip < 4; ip++)
#pragma unroll
                for (int j = 0; j < 4; j++)
                    unpack2(s2[ip][j], s[2 * ip][j], s[2 * ip + 1][j]);

            // masked online softmax update (row stats across 16-lane tx group)
            float scv[8];
#pragma unroll
            for (int i = 0; i < 8; i++) {
                int n = qt * 128 + ty * 8 + i;
                float4 mv = *(const float4*)(mb + (size_t)n * Gg + g0 + tx * 4);
                float mk[4] = {mv.x, mv.y, mv.z, mv.w};
#pragma unroll
                for (int j = 0; j < 4; j++)
                    s[i][j] = (mk[j] != 0.0f) ? s[i][j] * NORMS : -1e30f;
                float rm = fmaxf(fmaxf(s[i][0], s[i][1]), fmaxf(s[i][2], s[i][3]));
#pragma unroll
                for (int off = 8; off >= 1; off >>= 1)
                    rm = fmaxf(rm, __shfl_xor_sync(0xffffffffu, rm, off));
                float mn = fmaxf(m[i], rm);
                float sc = __expf(m[i] - mn);          // -1e30 - -1e30 -> exp(0)=1, acc==0 so safe
                float rs = 0.f;
#pragma unroll
                for (int j = 0; j < 4; j++) {
                    float p = (s[i][j] > -1e29f) ? __expf(s[i][j] - mn) : 0.f;
                    Ps[(tx * 4 + j) * 132 + ty * 8 + i] = p;
                    rs += p;
                }
#pragma unroll
                for (int off = 8; off >= 1; off >>= 1)
                    rs += __shfl_xor_sync(0xffffffffu, rs, off);
                den[i] = den[i] * sc + rs;
                m[i]   = mn;
                scv[i] = sc;
            }
            // rescale accumulators with packed multiply
#pragma unroll
            for (int ip = 0; ip < 4; ip++) {
                u64 sp = pack2(scv[2 * ip], scv[2 * ip + 1]);
#pragma unroll
                for (int j = 0; j < 4; j++) o2[ip][j] = fmul2(o2[ip][j], sp);
            }
            __syncthreads();

            // O += P V   (8q x 4v per thread), rows paired into f32x2
#pragma unroll 8
            for (int g = 0; g < 64; g++) {
                double2 p0 = *(const double2*)(Ps + g * 132 + ty * 8);
                double2 p1 = *(const double2*)(Ps + g * 132 + ty * 8 + 4);
                u64 pv2[4] = { d2u(p0.x), d2u(p0.y), d2u(p1.x), d2u(p1.y) };
                float4 vv = *(const float4*)(Vs + g * 68 + tx * 4);
                float vj[4] = {vv.x, vv.y, vv.z, vv.w};
#pragma unroll
                for (int j = 0; j < 4; j++) {
                    u64 vb = pack2(vj[j], vj[j]);
#pragma unroll
                    for (int ip = 0; ip < 4; ip++)
                        o2[ip][j] = ffma2(pv2[ip], vb, o2[ip][j]);
                }
            }
        }
        __syncthreads();  // all PV reads done before next c overwrites Qs tiles
    }

    // epilogue: normalize and write heads as (B,NQ,H,VD)
    float acc[8][4];
#pragma unroll
    for (int ip = 0; ip < 4; ip++)
#pragma unroll
        for (int j = 0; j < 4; j++)
            unpack2(o2[ip][j], acc[2 * ip][j], acc[2 * ip + 1][j]);
    size_t outbase = (size_t)(b * NQq + qt * 128 + ty * 8) * 512 + h * 64 + tx * 4;
#pragma unroll
    for (int i = 0; i < 8; i++) {
        float inv = (den[i] > 0.f) ? 1.f / den[i] : 0.f;
        float4 o = make_float4(acc[i][0] * inv, acc[i][1] * inv,
                               acc[i][2] * inv, acc[i][3] * inv);
        *(float4*)(g_Hd + outbase + (size_t)i * 512) = o;
    }
}

// ---------------- launch ---------------------------------------------------
extern "C" void kernel_launch(void* const* d_in, const int* in_sizes, int n_in,
                              void* d_out, int out_size) {
    const float* q    = (const float*)d_in[0];
    const float* attM = (const float*)d_in[1];
    const float* grpM = (const float*)d_in[2];
    const float* sdM  = (const float*)d_in[3];
    WPtrs wp;
    for (int i = 0; i < 12; i++) wp.w[i] = (const float*)d_in[4 + i];
    const float* wout = (const float*)d_in[16];
    float* out = (float*)d_out;

    void *pWcat, *pP, *pHd;
    cudaGetSymbolAddress(&pWcat, g_Wcat);
    cudaGetSymbolAddress(&pP, g_P);
    cudaGetSymbolAddress(&pHd, g_Hd);

    // 1. repack weights
    repack_kernel<<<(Dd * NCOL + 255) / 256, 256>>>(wp);
    // 2. transpose att mask
    mask_transpose_kernel<<<dim3(16, 16, 16), dim3(32, 32)>>>(attM);
    // 3. fused projection GEMM: [8192 x 512] * [512 x 6144]
    sgemm_kernel<<<dim3(NCOL / 128, ROWSM / 128), 256>>>(
        q, (const float*)pWcat, (float*)pP, ROWSM, NCOL, Dd);
    // 4. fused masked 4-branch attention
    cudaFuncSetAttribute(attn_kernel, cudaFuncAttributeMaxDynamicSharedMemorySize,
                         ATTN_SMEM_BYTES);
    attn_kernel<<<dim3(4, 128), 256, ATTN_SMEM_BYTES>>>(attM, grpM, sdM);
    // 5. output projection: [8192 x 512] * [512 x 512]
    sgemm_kernel<<<dim3(Ee / 128, ROWSM / 128), 256>>>(
        (const float*)pHd, wout, out, ROWSM, Ee, Dd);
}

// round 4
// speedup vs baseline: 1.3262x; 1.3255x over previous
#include <cuda_runtime.h>
#include <cuda_bf16.h>
#include <cstdint>

#define Hh   8
#define Bb   16
#define Gg   512
#define NQq  512
#define Dd   512
#define KDd  64
#define Ee   512
#define NCOL 6144           /* 12 * 512 */
#define ROWSM 8192          /* B * NQ   */
#define NORMS 0.125f

typedef unsigned long long u64;

// ---------------- packed fp32x2 helpers (kept for attention) --------------
__device__ __forceinline__ u64 ffma2(u64 a, u64 b, u64 c) {
    u64 d;
    asm("fma.rn.f32x2 %0, %1, %2, %3;" : "=l"(d) : "l"(a), "l"(b), "l"(c));
    return d;
}
__device__ __forceinline__ u64 fmul2(u64 a, u64 b) {
    u64 d;
    asm("mul.rn.f32x2 %0, %1, %2;" : "=l"(d) : "l"(a), "l"(b));
    return d;
}
__device__ __forceinline__ u64 pack2(float lo, float hi) {
    u64 d;
    asm("mov.b64 %0, {%1, %2};" : "=l"(d) : "f"(lo), "f"(hi));
    return d;
}
__device__ __forceinline__ void unpack2(u64 v, float& lo, float& hi) {
    asm("mov.b64 {%0, %1}, %2;" : "=f"(lo), "=f"(hi) : "l"(v));
}
__device__ __forceinline__ u64 d2u(double v) { return __double_as_longlong(v); }

// ---------------- mma.sync / ldmatrix helpers ------------------------------
__device__ __forceinline__ void ldsm4(uint32_t* d, uint32_t addr) {
    asm volatile("ldmatrix.sync.aligned.m8n8.x4.shared.b16 {%0,%1,%2,%3}, [%4];"
                 : "=r"(d[0]), "=r"(d[1]), "=r"(d[2]), "=r"(d[3]) : "r"(addr));
}
__device__ __forceinline__ void ldsm4t(uint32_t* d, uint32_t addr) {
    asm volatile("ldmatrix.sync.aligned.m8n8.x4.trans.shared.b16 {%0,%1,%2,%3}, [%4];"
                 : "=r"(d[0]), "=r"(d[1]), "=r"(d[2]), "=r"(d[3]) : "r"(addr));
}
__device__ __forceinline__ void mma_bf16(float* c, const uint32_t* a,
                                         uint32_t b0, uint32_t b1) {
    asm volatile(
        "mma.sync.aligned.m16n8k16.row.col.f32.bf16.bf16.f32 "
        "{%0,%1,%2,%3}, {%4,%5,%6,%7}, {%8,%9}, {%0,%1,%2,%3};"
        : "+f"(c[0]), "+f"(c[1]), "+f"(c[2]), "+f"(c[3])
        : "r"(a[0]), "r"(a[1]), "r"(a[2]), "r"(a[3]), "r"(b0), "r"(b1));
}

// ---------------- device scratch (static: allocation-guard safe) ----------
__device__ float g_P[(size_t)ROWSM * NCOL];         // projections, 201 MB
__device__ float g_attT[(size_t)Bb * NQq * Gg];     // transposed att mask
__device__ float g_Hd[(size_t)ROWSM * (Hh * KDd)];  // attention heads (B,NQ,H,VD)

__device__ __nv_bfloat16 g_Ahi[(size_t)ROWSM * Dd];   // q split
__device__ __nv_bfloat16 g_Alo[(size_t)ROWSM * Dd];
__device__ __nv_bfloat16 g_Whi[(size_t)Dd * NCOL];    // fused weights split
__device__ __nv_bfloat16 g_Wlo[(size_t)Dd * NCOL];
__device__ __nv_bfloat16 g_Ohi[Dd * Ee];              // W_out split
__device__ __nv_bfloat16 g_Olo[Dd * Ee];
__device__ __nv_bfloat16 g_Hhi[(size_t)ROWSM * Dd];   // heads split
__device__ __nv_bfloat16 g_Hlo[(size_t)ROWSM * Dd];

struct WPtrs { const float* w[12]; };

// ---------------- weight repack + split: 12 x (H,D,64) -> hi/lo [D][6144] --
__global__ void repack_split_kernel(WPtrs wp) {
    int idx = blockIdx.x * blockDim.x + threadIdx.x;
    if (idx >= Dd * NCOL) return;
    int d   = idx / NCOL;
    int col = idx - d * NCOL;
    int w   = col >> 9;
    int hk  = col & 511;
    int h   = hk >> 6;
    int k   = hk & 63;
    float x = wp.w[w][((size_t)h * Dd + d) * KDd + k];
    __nv_bfloat16 hi = __float2bfloat16_rn(x);
    g_Whi[idx] = hi;
    g_Wlo[idx] = __float2bfloat16_rn(x - __bfloat162float(hi));
}

// ---------------- generic fp32 -> bf16 hi/lo split -------------------------
__global__ void conv_split_kernel(const float* __restrict__ src,
                                  __nv_bfloat16* __restrict__ hi,
                                  __nv_bfloat16* __restrict__ lo, int n) {
    int i = blockIdx.x * blockDim.x + threadIdx.x;
    if (i >= n) return;
    float x = src[i];
    __nv_bfloat16 h = __float2bfloat16_rn(x);
    hi[i] = h;
    lo[i] = __float2bfloat16_rn(x - __bfloat162float(h));
}

// ---------------- att mask transpose: (B,G,NQ) -> (B,NQ,G) ----------------
__global__ void mask_transpose_kernel(const float* __restrict__ att) {
    __shared__ float t[32][33];
    int b  = blockIdx.z;
    int n0 = blockIdx.x * 32;
    int g0 = blockIdx.y * 32;
    const float* src = att + (size_t)b * Gg * NQq;
    t[threadIdx.y][threadIdx.x] = src[(size_t)(g0 + threadIdx.y) * NQq + n0 + threadIdx.x];
    __syncthreads();
    g_attT[(size_t)b * NQq * Gg + (size_t)(n0 + threadIdx.y) * Gg + g0 + threadIdx.x] =
        t[threadIdx.x][threadIdx.y];
}

// ---------------- bf16x3 split-MMA GEMM: C[M,N] = A[M,K] * B[K,N] ---------
// Block tile 64x64, 128 threads (4 warps in 2x2), warp tile 32x32.
// A planes stored [64][24] bf16 (pad), B planes [16][72] bf16 (pad).
__global__ __launch_bounds__(128) void mma_gemm_kernel(
    const __nv_bfloat16* __restrict__ Ahi, const __nv_bfloat16* __restrict__ Alo,
    const __nv_bfloat16* __restrict__ Bhi, const __nv_bfloat16* __restrict__ Blo,
    float* __restrict__ C, int M, int N, int K) {
    __shared__ __nv_bfloat16 Ash[2][64 * 24];
    __shared__ __nv_bfloat16 Bsh[2][16 * 72];

    int tid  = threadIdx.x;
    int lane = tid & 31;
    int wid  = tid >> 5;
    int wm   = wid >> 1;          // 0..1 -> m offset *32
    int wn   = wid & 1;           // 0..1 -> n offset *32

    int m0 = blockIdx.y * 64;
    int n0 = blockIdx.x * 64;

    const __nv_bfloat16* Ag[2] = { Ahi, Alo };
    const __nv_bfloat16* Bg[2] = { Bhi, Blo };

    float acc[2][4][4];
#pragma unroll
    for (int mf = 0; mf < 2; mf++)
#pragma unroll
        for (int nf = 0; nf < 4; nf++)
#pragma unroll
            for (int e = 0; e < 4; e++) acc[mf][nf][e] = 0.f;

    int ar = tid >> 1, ap = tid & 1;      // A loader: row 0..63, half 0..1
    int br = tid >> 3, bp = tid & 7;      // B loader: row 0..15, part 0..7

    uint32_t asm_base[2], bsm_base[2];
#pragma unroll
    for (int p = 0; p < 2; p++) {
        asm_base[p] = (uint32_t)__cvta_generic_to_shared(&Ash[p][0]);
        bsm_base[p] = (uint32_t)__cvta_generic_to_shared(&Bsh[p][0]);
    }

    for (int k0 = 0; k0 < K; k0 += 16) {
#pragma unroll
        for (int p = 0; p < 2; p++) {
            uint4 va = *(const uint4*)(Ag[p] + (size_t)(m0 + ar) * K + k0 + ap * 8);
            *(uint4*)(&Ash[p][ar * 24 + ap * 8]) = va;
            uint4 vb = *(const uint4*)(Bg[p] + (size_t)(k0 + br) * N + n0 + bp * 8);
            *(uint4*)(&Bsh[p][br * 72 + bp * 8]) = vb;
        }
        __syncthreads();

        uint32_t a[2][2][4];    // [plane][mfrag][4]
        uint32_t b[2][2][4];    // [plane][npair][4] -> nfrag 2*pair+{0,1}
#pragma unroll
        for (int p = 0; p < 2; p++) {
#pragma unroll
            for (int mf = 0; mf < 2; mf++) {
                uint32_t off = ((wm * 32 + mf * 16 + (lane & 15)) * 24 +
                                (lane >> 4) * 8) * 2;
                ldsm4(a[p][mf], asm_base[p] + off);
            }
#pragma unroll
            for (int pr = 0; pr < 2; pr++) {
                uint32_t off = ((lane & 15) * 72 + wn * 32 + pr * 16 +
                                (lane >> 4) * 8) * 2;
                ldsm4t(b[p][pr], bsm_base[p] + off);
            }
        }
#pragma unroll
        for (int mf = 0; mf < 2; mf++)
#pragma unroll
            for (int nf = 0; nf < 4; nf++) {
                int pr = nf >> 1, hh = nf & 1;
                // hi*hi + hi*lo + lo*hi
                mma_bf16(acc[mf][nf], a[0][mf], b[0][pr][2 * hh], b[0][pr][2 * hh + 1]);
                mma_bf16(acc[mf][nf], a[0][mf], b[1][pr][2 * hh], b[1][pr][2 * hh + 1]);
                mma_bf16(acc[mf][nf], a[1][mf], b[0][pr][2 * hh], b[0][pr][2 * hh + 1]);
            }
        __syncthreads();
    }

    // epilogue
#pragma unroll
    for (int mf = 0; mf < 2; mf++) {
        int gm = m0 + wm * 32 + mf * 16 + (lane >> 2);
#pragma unroll
        for (int nf = 0; nf < 4; nf++) {
            int gn = n0 + wn * 32 + nf * 8 + (lane & 3) * 2;
            *(float2*)(C + (size_t)gm * N + gn) =
                make_float2(acc[mf][nf][0], acc[mf][nf][1]);
            *(float2*)(C + (size_t)(gm + 8) * N + gn) =
                make_float2(acc[mf][nf][2], acc[mf][nf][3]);
        }
    }
}

// ---------------- fused attention (flash-style online softmax) ------------
#define ATTN_SMEM_FLOATS (64 * 132 + 64 * 68 + 64 * 68 + 64 * 132)
#define ATTN_SMEM_BYTES  (ATTN_SMEM_FLOATS * 4)

__global__ __launch_bounds__(256) void attn_kernel(
    const float* __restrict__ attm,
    const float* __restrict__ gmk,
    const float* __restrict__ sd) {
    extern __shared__ float smbuf[];
    float* Qs = smbuf;                 // [k(64)][q(128)] pad 132
    float* Ks = Qs + 64 * 132;         // [k(64)][g(64)]  pad 68
    float* Vs = Ks + 64 * 68;          // [g(64)][v(64)]  pad 68
    float* Ps = Vs + 64 * 68;          // [g(64)][q(128)] pad 132

    int qt = blockIdx.x;
    int hb = blockIdx.y;
    int h  = hb >> 4;
    int b  = hb & 15;
    int tid = threadIdx.x;
    int ty = tid >> 4, tx = tid & 15;

    float m[8], den[8];
    u64 o2[4][4];
#pragma unroll
    for (int i = 0; i < 8; i++) { m[i] = -1e30f; den[i] = 0.f; }
#pragma unroll
    for (int ip = 0; ip < 4; ip++)
#pragma unroll
        for (int j = 0; j < 4; j++) o2[ip][j] = 0ULL;

    const size_t mboff = (size_t)b * NQq * Gg;
    const float* mbase[4] = { sd + mboff, g_attT + mboff, attm + mboff, gmk + mboff };

    for (int c = 0; c < 4; c++) {
        const float* Qg = g_P + (size_t)(b * NQq + qt * 128) * NCOL + (3 * c) * 512 + h * 64;
#pragma unroll
        for (int l = 0; l < 8; l++) {
            int i  = tid + l * 256;
            int r  = i >> 4;
            int c4 = (i & 15) << 2;
            float4 v = *(const float4*)(Qg + (size_t)r * NCOL + c4);
            Qs[(c4 + 0) * 132 + r] = v.x;
            Qs[(c4 + 1) * 132 + r] = v.y;
            Qs[(c4 + 2) * 132 + r] = v.z;
            Qs[(c4 + 3) * 132 + r] = v.w;
        }
        const float* mb = mbase[c];

        for (int g0 = 0; g0 < Gg; g0 += 64) {
            __syncthreads();
            const float* Kg = g_P + (size_t)(b * NQq + g0) * NCOL + (3 * c + 1) * 512 + h * 64;
            const float* Vg = g_P + (size_t)(b * NQq + g0) * NCOL + (3 * c + 2) * 512 + h * 64;
#pragma unroll
            for (int l = 0; l < 4; l++) {
                int i  = tid + l * 256;
                int r  = i >> 4;
                int c4 = (i & 15) << 2;
                float4 kv = *(const float4*)(Kg + (size_t)r * NCOL + c4);
                Ks[(c4 + 0) * 68 + r] = kv.x;
                Ks[(c4 + 1) * 68 + r] = kv.y;
                Ks[(c4 + 2) * 68 + r] = kv.z;
                Ks[(c4 + 3) * 68 + r] = kv.w;
                float4 vv = *(const float4*)(Vg + (size_t)r * NCOL + c4);
                *(float4*)(Vs + r * 68 + c4) = vv;
            }
            __syncthreads();

            u64 s2[4][4];
#pragma unroll
            for (int ip = 0; ip < 4; ip++)
#pragma unroll
                for (int j = 0; j < 4; j++) s2[ip][j] = 0ULL;
#pragma unroll 8
            for (int k = 0; k < 64; k++) {
                double2 ap0 = *(const double2*)(Qs + k * 132 + ty * 8);
                double2 ap1 = *(const double2*)(Qs + k * 132 + ty * 8 + 4);
                u64 av2[4] = { d2u(ap0.x), d2u(ap0.y), d2u(ap1.x), d2u(ap1.y) };
                float4 bb = *(const float4*)(Ks + k * 68 + tx * 4);
                float bv[4] = {bb.x, bb.y, bb.z, bb.w};
#pragma unroll
                for (int j = 0; j < 4; j++) {
                    u64 bc = pack2(bv[j], bv[j]);
#pragma unroll
                    for (int ip = 0; ip < 4; ip++)
                        s2[ip][j] = ffma2(av2[ip], bc, s2[ip][j]);
                }
            }
            float s[8][4];
#pragma unroll
            for (int ip = 0; ip < 4; ip++)
#pragma unroll
                for (int j = 0; j < 4; j++)
                    unpack2(s2[ip][j], s[2 * ip][j], s[2 * ip + 1][j]);

            float scv[8];
#pragma unroll
            for (int i = 0; i < 8; i++) {
                int n = qt * 128 + ty * 8 + i;
                float4 mv = *(const float4*)(mb + (size_t)n * Gg + g0 + tx * 4);
                float mk[4] = {mv.x, mv.y, mv.z, mv.w};
#pragma unroll
                for (int j = 0; j < 4; j++)
                    s[i][j] = (mk[j] != 0.0f) ? s[i][j] * NORMS : -1e30f;
                float rm = fmaxf(fmaxf(s[i][0], s[i][1]), fmaxf(s[i][2], s[i][3]));
#pragma unroll
                for (int off = 8; off >= 1; off >>= 1)
                    rm = fmaxf(rm, __shfl_xor_sync(0xffffffffu, rm, off));
                float mn = fmaxf(m[i], rm);
                float sc = __expf(m[i] - mn);
                float rs = 0.f;
#pragma unroll
                for (int j = 0; j < 4; j++) {
                    float p = (s[i][j] > -1e29f) ? __expf(s[i][j] - mn) : 0.f;
                    Ps[(tx * 4 + j) * 132 + ty * 8 + i] = p;
                    rs += p;
                }
#pragma unroll
                for (int off = 8; off >= 1; off >>= 1)
                    rs += __shfl_xor_sync(0xffffffffu, rs, off);
                den[i] = den[i] * sc + rs;
                m[i]   = mn;
                scv[i] = sc;
            }
#pragma unroll
            for (int ip = 0; ip < 4; ip++) {
                u64 sp = pack2(scv[2 * ip], scv[2 * ip + 1]);
#pragma unroll
                for (int j = 0; j < 4; j++) o2[ip][j] = fmul2(o2[ip][j], sp);
            }
            __syncthreads();

#pragma unroll 8
            for (int g = 0; g < 64; g++) {
                double2 p0 = *(const double2*)(Ps + g * 132 + ty * 8);
                double2 p1 = *(const double2*)(Ps + g * 132 + ty * 8 + 4);
                u64 pv2[4] = { d2u(p0.x), d2u(p0.y), d2u(p1.x), d2u(p1.y) };
                float4 vv = *(const float4*)(Vs + g * 68 + tx * 4);
                float vj[4] = {vv.x, vv.y, vv.z, vv.w};
#pragma unroll
                for (int j = 0; j < 4; j++) {
                    u64 vb = pack2(vj[j], vj[j]);
#pragma unroll
                    for (int ip = 0; ip < 4; ip++)
                        o2[ip][j] = ffma2(pv2[ip], vb, o2[ip][j]);
                }
            }
        }
        __syncthreads();
    }

    float acc[8][4];
#pragma unroll
    for (int ip = 0; ip < 4; ip++)
#pragma unroll
        for (int j = 0; j < 4; j++)
            unpack2(o2[ip][j], acc[2 * ip][j], acc[2 * ip + 1][j]);
    size_t outbase = (size_t)(b * NQq + qt * 128 + ty * 8) * 512 + h * 64 + tx * 4;
#pragma unroll
    for (int i = 0; i < 8; i++) {
        float inv = (den[i] > 0.f) ? 1.f / den[i] : 0.f;
        float4 o = make_float4(acc[i][0] * inv, acc[i][1] * inv,
                               acc[i][2] * inv, acc[i][3] * inv);
        *(float4*)(g_Hd + outbase + (size_t)i * 512) = o;
    }
}

// ---------------- launch ---------------------------------------------------
extern "C" void kernel_launch(void* const* d_in, const int* in_sizes, int n_in,
                              void* d_out, int out_size) {
    const float* q    = (const float*)d_in[0];
    const float* attM = (const float*)d_in[1];
    const float* grpM = (const float*)d_in[2];
    const float* sdM  = (const float*)d_in[3];
    WPtrs wp;
    for (int i = 0; i < 12; i++) wp.w[i] = (const float*)d_in[4 + i];
    const float* wout = (const float*)d_in[16];
    float* out = (float*)d_out;

    void *pP, *pHd, *pAhi, *pAlo, *pWhi, *pWlo, *pOhi, *pOlo, *pHhi, *pHlo;
    cudaGetSymbolAddress(&pP, g_P);
    cudaGetSymbolAddress(&pHd, g_Hd);
    cudaGetSymbolAddress(&pAhi, g_Ahi);
    cudaGetSymbolAddress(&pAlo, g_Alo);
    cudaGetSymbolAddress(&pWhi, g_Whi);
    cudaGetSymbolAddress(&pWlo, g_Wlo);
    cudaGetSymbolAddress(&pOhi, g_Ohi);
    cudaGetSymbolAddress(&pOlo, g_Olo);
    cudaGetSymbolAddress(&pHhi, g_Hhi);
    cudaGetSymbolAddress(&pHlo, g_Hlo);

    // 1. repack + split weights
    repack_split_kernel<<<(Dd * NCOL + 255) / 256, 256>>>(wp);
    // 2. split q and W_out
    conv_split_kernel<<<(ROWSM * Dd + 255) / 256, 256>>>(
        q, (__nv_bfloat16*)pAhi, (__nv_bfloat16*)pAlo, ROWSM * Dd);
    conv_split_kernel<<<(Dd * Ee + 255) / 256, 256>>>(
        wout, (__nv_bfloat16*)pOhi, (__nv_bfloat16*)pOlo, Dd * Ee);
    // 3. transpose att mask
    mask_transpose_kernel<<<dim3(16, 16, 16), dim3(32, 32)>>>(attM);
    // 4. fused projection GEMM (tensor cores, bf16x3): [8192x512]*[512x6144]
    mma_gemm_kernel<<<dim3(NCOL / 64, ROWSM / 64), 128>>>(
        (const __nv_bfloat16*)pAhi, (const __nv_bfloat16*)pAlo,
        (const __nv_bfloat16*)pWhi, (const __nv_bfloat16*)pWlo,
        (float*)pP, ROWSM, NCOL, Dd);
    // 5. fused masked 4-branch attention
    cudaFuncSetAttribute(attn_kernel, cudaFuncAttributeMaxDynamicSharedMemorySize,
                         ATTN_SMEM_BYTES);
    attn_kernel<<<dim3(4, 128), 256, ATTN_SMEM_BYTES>>>(attM, grpM, sdM);
    // 6. split heads, output GEMM (tensor cores): [8192x512]*[512x512]
    conv_split_kernel<<<(ROWSM * Dd + 255) / 256, 256>>>(
        (const float*)pHd, (__nv_bfloat16*)pHhi, (__nv_bfloat16*)pHlo, ROWSM * Dd);
    mma_gemm_kernel<<<dim3(Ee / 64, ROWSM / 64), 128>>>(
        (const __nv_bfloat16*)pHhi, (const __nv_bfloat16*)pHlo,
        (const __nv_bfloat16*)pOhi, (const __nv_bfloat16*)pOlo,
        out, ROWSM, Ee, Dd);
}

// round 5
// speedup vs baseline: 1.9687x; 1.4845x over previous
#include <cuda_runtime.h>
#include <cuda_bf16.h>
#include <cstdint>

#define Hh   8
#define Bb   16
#define Gg   512
#define NQq  512
#define Dd   512
#define KDd  64
#define Ee   512
#define NCOL 6144           /* 12 * 512 */
#define ROWSM 8192          /* B * NQ   */
#define NORMS 0.125f

typedef unsigned long long u64;

// ---------------- mma.sync / ldmatrix helpers ------------------------------
__device__ __forceinline__ void ldsm4(uint32_t* d, uint32_t addr) {
    asm volatile("ldmatrix.sync.aligned.m8n8.x4.shared.b16 {%0,%1,%2,%3}, [%4];"
                 : "=r"(d[0]), "=r"(d[1]), "=r"(d[2]), "=r"(d[3]) : "r"(addr));
}
__device__ __forceinline__ void ldsm4t(uint32_t* d, uint32_t addr) {
    asm volatile("ldmatrix.sync.aligned.m8n8.x4.trans.shared.b16 {%0,%1,%2,%3}, [%4];"
                 : "=r"(d[0]), "=r"(d[1]), "=r"(d[2]), "=r"(d[3]) : "r"(addr));
}
__device__ __forceinline__ void mma_bf16(float* c, const uint32_t* a,
                                         uint32_t b0, uint32_t b1) {
    asm volatile(
        "mma.sync.aligned.m16n8k16.row.col.f32.bf16.bf16.f32 "
        "{%0,%1,%2,%3}, {%4,%5,%6,%7}, {%8,%9}, {%0,%1,%2,%3};"
        : "+f"(c[0]), "+f"(c[1]), "+f"(c[2]), "+f"(c[3])
        : "r"(a[0]), "r"(a[1]), "r"(a[2]), "r"(a[3]), "r"(b0), "r"(b1));
}
// pack two fp32 (lo_val -> low half, hi_val -> high half) as bf16x2, and residual
__device__ __forceinline__ void split_pair(float v0, float v1,
                                           uint32_t& hi, uint32_t& lo) {
    uint32_t h;
    asm("cvt.rn.bf16x2.f32 %0, %1, %2;" : "=r"(h) : "f"(v1), "f"(v0));
    float f0 = __uint_as_float(h << 16);
    float f1 = __uint_as_float(h & 0xFFFF0000u);
    uint32_t l;
    asm("cvt.rn.bf16x2.f32 %0, %1, %2;" : "=r"(l) : "f"(v1 - f1), "f"(v0 - f0));
    hi = h; lo = l;
}

// ---------------- device scratch (static: allocation-guard safe) ----------
__device__ __nv_bfloat16 g_Phi[(size_t)ROWSM * NCOL];  // projections hi
__device__ __nv_bfloat16 g_Plo[(size_t)ROWSM * NCOL];  // projections lo
__device__ u64 g_mask[(size_t)Bb * 4 * NQq * 8];       // packed masks (64 keys/word)

__device__ __nv_bfloat16 g_Ahi[(size_t)ROWSM * Dd];    // q split
__device__ __nv_bfloat16 g_Alo[(size_t)ROWSM * Dd];
__device__ __nv_bfloat16 g_Whi[(size_t)Dd * NCOL];     // fused weights split
__device__ __nv_bfloat16 g_Wlo[(size_t)Dd * NCOL];
__device__ __nv_bfloat16 g_Ohi[Dd * Ee];               // W_out split
__device__ __nv_bfloat16 g_Olo[Dd * Ee];
__device__ __nv_bfloat16 g_Hhi[(size_t)ROWSM * Dd];    // heads split (B,NQ,H,VD)
__device__ __nv_bfloat16 g_Hlo[(size_t)ROWSM * Dd];

struct WPtrs { const float* w[12]; };

// ---------------- weight repack + split: 12 x (H,D,64) -> hi/lo [D][6144] --
__global__ void repack_split_kernel(WPtrs wp) {
    int idx = blockIdx.x * blockDim.x + threadIdx.x;
    if (idx >= Dd * NCOL) return;
    int d   = idx / NCOL;
    int col = idx - d * NCOL;
    int w   = col >> 9;
    int hk  = col & 511;
    int h   = hk >> 6;
    int k   = hk & 63;
    float x = wp.w[w][((size_t)h * Dd + d) * KDd + k];
    __nv_bfloat16 hi = __float2bfloat16_rn(x);
    g_Whi[idx] = hi;
    g_Wlo[idx] = __float2bfloat16_rn(x - __bfloat162float(hi));
}

// ---------------- generic fp32 -> bf16 hi/lo split -------------------------
__global__ void conv_split_kernel(const float* __restrict__ src,
                                  __nv_bfloat16* __restrict__ hi,
                                  __nv_bfloat16* __restrict__ lo, int n) {
    int i = blockIdx.x * blockDim.x + threadIdx.x;
    if (i >= n) return;
    float x = src[i];
    __nv_bfloat16 h = __float2bfloat16_rn(x);
    hi[i] = h;
    lo[i] = __float2bfloat16_rn(x - __bfloat162float(h));
}

// ---------------- mask pack: 4 branch masks -> u64 bitmasks ---------------
// word index: ((b*4 + c)*512 + q)*8 + tile ; bit j = mask(q, tile*64+j)
__global__ void mask_pack_kernel(const float* __restrict__ attm,
                                 const float* __restrict__ gmk,
                                 const float* __restrict__ sd) {
    int idx = blockIdx.x * blockDim.x + threadIdx.x;   // 262144 total
    int q    = idx & 511;
    int tile = (idx >> 9) & 7;
    int c    = (idx >> 12) & 3;
    int b    = idx >> 14;
    u64 w = 0;
#pragma unroll 16
    for (int j = 0; j < 64; j++) {
        int g = tile * 64 + j;
        float v;
        if (c == 0)      v = sd[((size_t)b * 512 + q) * 512 + g];
        else if (c == 1) v = attm[((size_t)b * 512 + g) * 512 + q];
        else if (c == 2) v = attm[((size_t)b * 512 + q) * 512 + g];
        else             v = gmk[((size_t)b * 512 + q) * 512 + g];
        w |= (u64)(v != 0.0f) << j;
    }
    g_mask[(((size_t)b * 4 + c) * 512 + q) * 8 + tile] = w;
}

// ---------------- bf16x3 split-MMA GEMM: C[M,N] = A[M,K] * B[K,N] ---------
// Block 64x64, 128 threads (2x2 warps), warp tile 32x32.
// bf16out=0: write fp32 C. bf16out=1: write Chi/Clo bf16 planes.
__global__ __launch_bounds__(128) void mma_gemm_kernel(
    const __nv_bfloat16* __restrict__ Ahi, const __nv_bfloat16* __restrict__ Alo,
    const __nv_bfloat16* __restrict__ Bhi, const __nv_bfloat16* __restrict__ Blo,
    float* __restrict__ C,
    __nv_bfloat16* __restrict__ Chi, __nv_bfloat16* __restrict__ Clo,
    int M, int N, int K, int bf16out) {
    __shared__ __nv_bfloat16 Ash[2][64 * 24];
    __shared__ __nv_bfloat16 Bsh[2][16 * 72];

    int tid  = threadIdx.x;
    int lane = tid & 31;
    int wid  = tid >> 5;
    int wm   = wid >> 1;
    int wn   = wid & 1;

    int m0 = blockIdx.y * 64;
    int n0 = blockIdx.x * 64;

    const __nv_bfloat16* Ag[2] = { Ahi, Alo };
    const __nv_bfloat16* Bg[2] = { Bhi, Blo };

    float acc[2][4][4];
#pragma unroll
    for (int mf = 0; mf < 2; mf++)
#pragma unroll
        for (int nf = 0; nf < 4; nf++)
#pragma unroll
            for (int e = 0; e < 4; e++) acc[mf][nf][e] = 0.f;

    int ar = tid >> 1, ap = tid & 1;
    int br = tid >> 3, bp = tid & 7;

    uint32_t asm_base[2], bsm_base[2];
#pragma unroll
    for (int p = 0; p < 2; p++) {
        asm_base[p] = (uint32_t)__cvta_generic_to_shared(&Ash[p][0]);
        bsm_base[p] = (uint32_t)__cvta_generic_to_shared(&Bsh[p][0]);
    }

    for (int k0 = 0; k0 < K; k0 += 16) {
#pragma unroll
        for (int p = 0; p < 2; p++) {
            uint4 va = *(const uint4*)(Ag[p] + (size_t)(m0 + ar) * K + k0 + ap * 8);
            *(uint4*)(&Ash[p][ar * 24 + ap * 8]) = va;
            uint4 vb = *(const uint4*)(Bg[p] + (size_t)(k0 + br) * N + n0 + bp * 8);
            *(uint4*)(&Bsh[p][br * 72 + bp * 8]) = vb;
        }
        __syncthreads();

        uint32_t a[2][2][4];
        uint32_t b[2][2][4];
#pragma unroll
        for (int p = 0; p < 2; p++) {
#pragma unroll
            for (int mf = 0; mf < 2; mf++) {
                uint32_t off = ((wm * 32 + mf * 16 + (lane & 15)) * 24 +
                                (lane >> 4) * 8) * 2;
                ldsm4(a[p][mf], asm_base[p] + off);
            }
#pragma unroll
            for (int pr = 0; pr < 2; pr++) {
                uint32_t off = ((lane & 15) * 72 + wn * 32 + pr * 16 +
                                (lane >> 4) * 8) * 2;
                ldsm4t(b[p][pr], bsm_base[p] + off);
            }
        }
#pragma unroll
        for (int mf = 0; mf < 2; mf++)
#pragma unroll
            for (int nf = 0; nf < 4; nf++) {
                int pr = nf >> 1, hh = nf & 1;
                mma_bf16(acc[mf][nf], a[0][mf], b[0][pr][2 * hh], b[0][pr][2 * hh + 1]);
                mma_bf16(acc[mf][nf], a[0][mf], b[1][pr][2 * hh], b[1][pr][2 * hh + 1]);
                mma_bf16(acc[mf][nf], a[1][mf], b[0][pr][2 * hh], b[0][pr][2 * hh + 1]);
            }
        __syncthreads();
    }

#pragma unroll
    for (int mf = 0; mf < 2; mf++) {
        int gm = m0 + wm * 32 + mf * 16 + (lane >> 2);
#pragma unroll
        for (int nf = 0; nf < 4; nf++) {
            int gn = n0 + wn * 32 + nf * 8 + (lane & 3) * 2;
            if (bf16out) {
                uint32_t h2, l2;
                split_pair(acc[mf][nf][0], acc[mf][nf][1], h2, l2);
                *(uint32_t*)(Chi + (size_t)gm * N + gn) = h2;
                *(uint32_t*)(Clo + (size_t)gm * N + gn) = l2;
                split_pair(acc[mf][nf][2], acc[mf][nf][3], h2, l2);
                *(uint32_t*)(Chi + (size_t)(gm + 8) * N + gn) = h2;
                *(uint32_t*)(Clo + (size_t)(gm + 8) * N + gn) = l2;
            } else {
                *(float2*)(C + (size_t)gm * N + gn) =
                    make_float2(acc[mf][nf][0], acc[mf][nf][1]);
                *(float2*)(C + (size_t)(gm + 8) * N + gn) =
                    make_float2(acc[mf][nf][2], acc[mf][nf][3]);
            }
        }
    }
}

// ---------------- tensor-core fused attention ------------------------------
// Block: 128 queries x one (h,b); 4 warps, each 32 q x 64 keys.
// QK^T and PV via m16n8k16 bf16x3 split. Online softmax in fragments.
#define QSTR 72
#define ATTN_SMEM ((128 * QSTR * 2 + 64 * QSTR * 4) * 2)   /* 73728 B */

__global__ __launch_bounds__(128) void attn_mma_kernel() {
    extern __shared__ __nv_bfloat16 sm[];
    __nv_bfloat16* Qhi = sm;
    __nv_bfloat16* Qlo = Qhi + 128 * QSTR;
    __nv_bfloat16* Khi = Qlo + 128 * QSTR;
    __nv_bfloat16* Klo = Khi + 64 * QSTR;
    __nv_bfloat16* Vhi = Klo + 64 * QSTR;
    __nv_bfloat16* Vlo = Vhi + 64 * QSTR;

    int qt = blockIdx.x;               // 0..3
    int hb = blockIdx.y;               // 0..127
    int h  = hb >> 4;
    int b  = hb & 15;
    int tid  = threadIdx.x;
    int lane = tid & 31;
    int wq   = tid >> 5;               // warp: q-rows [wq*32, wq*32+32)

    uint32_t qhi_b = (uint32_t)__cvta_generic_to_shared(Qhi);
    uint32_t qlo_b = (uint32_t)__cvta_generic_to_shared(Qlo);
    uint32_t khi_b = (uint32_t)__cvta_generic_to_shared(Khi);
    uint32_t klo_b = (uint32_t)__cvta_generic_to_shared(Klo);
    uint32_t vhi_b = (uint32_t)__cvta_generic_to_shared(Vhi);
    uint32_t vlo_b = (uint32_t)__cvta_generic_to_shared(Vlo);

    float o[2][8][4];
    float mrow[2][2], den[2][2];
#pragma unroll
    for (int mf = 0; mf < 2; mf++) {
#pragma unroll
        for (int vf = 0; vf < 8; vf++)
#pragma unroll
            for (int e = 0; e < 4; e++) o[mf][vf][e] = 0.f;
        mrow[mf][0] = mrow[mf][1] = -1e30f;
        den[mf][0] = den[mf][1] = 0.f;
    }

    int ldr = tid >> 3;                // 0..15
    int c8  = tid & 7;                 // 16B chunk

    for (int c = 0; c < 4; c++) {
        __syncthreads();
        // load Q tile 128x64 (hi/lo)
        {
            const __nv_bfloat16* Qg = g_Phi + (size_t)(b * 512 + qt * 128) * NCOL
                                      + (3 * c) * 512 + h * 64;
            const __nv_bfloat16* Qg2 = g_Plo + (size_t)(b * 512 + qt * 128) * NCOL
                                      + (3 * c) * 512 + h * 64;
#pragma unroll
            for (int it = 0; it < 8; it++) {
                int row = ldr + it * 16;
                *(uint4*)(Qhi + row * QSTR + c8 * 8) =
                    *(const uint4*)(Qg + (size_t)row * NCOL + c8 * 8);
                *(uint4*)(Qlo + row * QSTR + c8 * 8) =
                    *(const uint4*)(Qg2 + (size_t)row * NCOL + c8 * 8);
            }
        }
        size_t mrow_base = (((size_t)b * 4 + c) * 512 + qt * 128) * 8;

        for (int g0t = 0; g0t < 8; g0t++) {
            __syncthreads();
            // load K,V tiles 64x64 (hi/lo)
            {
                size_t gbase = (size_t)(b * 512 + g0t * 64) * NCOL + h * 64 + c8 * 8;
                const __nv_bfloat16* KgH = g_Phi + gbase + (3 * c + 1) * 512;
                const __nv_bfloat16* KgL = g_Plo + gbase + (3 * c + 1) * 512;
                const __nv_bfloat16* VgH = g_Phi + gbase + (3 * c + 2) * 512;
                const __nv_bfloat16* VgL = g_Plo + gbase + (3 * c + 2) * 512;
#pragma unroll
                for (int it = 0; it < 4; it++) {
                    int row = ldr + it * 16;
                    *(uint4*)(Khi + row * QSTR + c8 * 8) = *(const uint4*)(KgH + (size_t)row * NCOL);
                    *(uint4*)(Klo + row * QSTR + c8 * 8) = *(const uint4*)(KgL + (size_t)row * NCOL);
                    *(uint4*)(Vhi + row * QSTR + c8 * 8) = *(const uint4*)(VgH + (size_t)row * NCOL);
                    *(uint4*)(Vlo + row * QSTR + c8 * 8) = *(const uint4*)(VgL + (size_t)row * NCOL);
                }
            }
            __syncthreads();

            // mask words (one u64 per row-group)
            u64 mw[2][2];
#pragma unroll
            for (int mf = 0; mf < 2; mf++)
#pragma unroll
                for (int hf = 0; hf < 2; hf++) {
                    int ql = wq * 32 + mf * 16 + (lane >> 2) + 8 * hf;
                    mw[mf][hf] = g_mask[mrow_base + (size_t)ql * 8 + g0t];
                }

            // ---- S = Q K^T (bf16x3) ----
            float s[2][8][4];
#pragma unroll
            for (int mf = 0; mf < 2; mf++)
#pragma unroll
                for (int nf = 0; nf < 8; nf++)
#pragma unroll
                    for (int e = 0; e < 4; e++) s[mf][nf][e] = 0.f;

#pragma unroll
            for (int ks = 0; ks < 4; ks++) {
                uint32_t ah[2][4], al[2][4];
#pragma unroll
                for (int mf = 0; mf < 2; mf++) {
                    uint32_t off = ((wq * 32 + mf * 16 + (lane & 15)) * QSTR +
                                    ks * 16 + (lane >> 4) * 8) * 2;
                    ldsm4(ah[mf], qhi_b + off);
                    ldsm4(al[mf], qlo_b + off);
                }
#pragma unroll
                for (int pr = 0; pr < 4; pr++) {
                    uint32_t off = ((pr * 16 + (lane & 7) + ((lane >> 4) & 1) * 8) * QSTR +
                                    ks * 16 + ((lane >> 3) & 1) * 8) * 2;
                    uint32_t kh[4], kl[4];
                    ldsm4(kh, khi_b + off);
                    ldsm4(kl, klo_b + off);
#pragma unroll
                    for (int mf = 0; mf < 2; mf++) {
                        mma_bf16(s[mf][2 * pr],     ah[mf], kh[0], kh[1]);
                        mma_bf16(s[mf][2 * pr],     ah[mf], kl[0], kl[1]);
                        mma_bf16(s[mf][2 * pr],     al[mf], kh[0], kh[1]);
                        mma_bf16(s[mf][2 * pr + 1], ah[mf], kh[2], kh[3]);
                        mma_bf16(s[mf][2 * pr + 1], ah[mf], kl[2], kl[3]);
                        mma_bf16(s[mf][2 * pr + 1], al[mf], kh[2], kh[3]);
                    }
                }
            }

            // ---- masked online softmax in fragments ----
#pragma unroll
            for (int mf = 0; mf < 2; mf++)
#pragma unroll
                for (int hf = 0; hf < 2; hf++) {
                    int i0 = 2 * hf;
                    u64 w = mw[mf][hf];
                    int sb = 2 * (lane & 3);
                    float rm = -1e30f;
#pragma unroll
                    for (int nf = 0; nf < 8; nf++) {
                        uint32_t bits = (uint32_t)(w >> (nf * 8 + sb)) & 3u;
                        float v0 = (bits & 1u) ? s[mf][nf][i0] * NORMS : -1e30f;
                        float v1 = (bits & 2u) ? s[mf][nf][i0 + 1] * NORMS : -1e30f;
                        s[mf][nf][i0]     = v0;
                        s[mf][nf][i0 + 1] = v1;
                        rm = fmaxf(rm, fmaxf(v0, v1));
                    }
                    rm = fmaxf(rm, __shfl_xor_sync(0xffffffffu, rm, 1));
                    rm = fmaxf(rm, __shfl_xor_sync(0xffffffffu, rm, 2));
                    float mo = mrow[mf][hf];
                    float mn = fmaxf(mo, rm);
                    float sc = __expf(mo - mn);
                    float rs = 0.f;
#pragma unroll
                    for (int nf = 0; nf < 8; nf++) {
                        float v0 = s[mf][nf][i0];
                        float v1 = s[mf][nf][i0 + 1];
                        float p0 = (v0 > -1e29f) ? __expf(v0 - mn) : 0.f;
                        float p1 = (v1 > -1e29f) ? __expf(v1 - mn) : 0.f;
                        s[mf][nf][i0]     = p0;
                        s[mf][nf][i0 + 1] = p1;
                        rs += p0 + p1;
                    }
                    rs += __shfl_xor_sync(0xffffffffu, rs, 1);
                    rs += __shfl_xor_sync(0xffffffffu, rs, 2);
                    den[mf][hf] = den[mf][hf] * sc + rs;
                    mrow[mf][hf] = mn;
#pragma unroll
                    for (int vf = 0; vf < 8; vf++) {
                        o[mf][vf][i0]     *= sc;
                        o[mf][vf][i0 + 1] *= sc;
                    }
                }

            // ---- O += P V (P from regs, bf16x3) ----
#pragma unroll
            for (int ks = 0; ks < 4; ks++) {
                uint32_t ph[2][4], pl[2][4];
#pragma unroll
                for (int mf = 0; mf < 2; mf++) {
                    split_pair(s[mf][2 * ks][0],     s[mf][2 * ks][1],     ph[mf][0], pl[mf][0]);
                    split_pair(s[mf][2 * ks][2],     s[mf][2 * ks][3],     ph[mf][1], pl[mf][1]);
                    split_pair(s[mf][2 * ks + 1][0], s[mf][2 * ks + 1][1], ph[mf][2], pl[mf][2]);
                    split_pair(s[mf][2 * ks + 1][2], s[mf][2 * ks + 1][3], ph[mf][3], pl[mf][3]);
                }
#pragma unroll
                for (int pr = 0; pr < 4; pr++) {
                    uint32_t off = ((ks * 16 + (lane & 15)) * QSTR +
                                    pr * 16 + (lane >> 4) * 8) * 2;
                    uint32_t vh[4], vl[4];
                    ldsm4t(vh, vhi_b + off);
                    ldsm4t(vl, vlo_b + off);
#pragma unroll
                    for (int mf = 0; mf < 2; mf++) {
                        mma_bf16(o[mf][2 * pr],     ph[mf], vh[0], vh[1]);
                        mma_bf16(o[mf][2 * pr],     ph[mf], vl[0], vl[1]);
                        mma_bf16(o[mf][2 * pr],     pl[mf], vh[0], vh[1]);
                        mma_bf16(o[mf][2 * pr + 1], ph[mf], vh[2], vh[3]);
                        mma_bf16(o[mf][2 * pr + 1], ph[mf], vl[2], vl[3]);
                        mma_bf16(o[mf][2 * pr + 1], pl[mf], vh[2], vh[3]);
                    }
                }
            }
        }
    }

    // epilogue: normalize, split to bf16 hi/lo, write heads (B,NQ,H,VD)
#pragma unroll
    for (int mf = 0; mf < 2; mf++)
#pragma unroll
        for (int hf = 0; hf < 2; hf++) {
            int ql = wq * 32 + mf * 16 + (lane >> 2) + 8 * hf;
            float dv = den[mf][hf];
            float inv = (dv > 0.f) ? 1.f / dv : 0.f;
            size_t base = ((size_t)(b * 512 + qt * 128 + ql)) * 512 + h * 64;
#pragma unroll
            for (int vf = 0; vf < 8; vf++) {
                float v0 = o[mf][vf][2 * hf] * inv;
                float v1 = o[mf][vf][2 * hf + 1] * inv;
                uint32_t h2, l2;
                split_pair(v0, v1, h2, l2);
                int col = vf * 8 + 2 * (lane & 3);
                *(uint32_t*)(g_Hhi + base + col) = h2;
                *(uint32_t*)(g_Hlo + base + col) = l2;
            }
        }
}

// ---------------- launch ---------------------------------------------------
extern "C" void kernel_launch(void* const* d_in, const int* in_sizes, int n_in,
                              void* d_out, int out_size) {
    const float* q    = (const float*)d_in[0];
    const float* attM = (const float*)d_in[1];
    const float* grpM = (const float*)d_in[2];
    const float* sdM  = (const float*)d_in[3];
    WPtrs wp;
    for (int i = 0; i < 12; i++) wp.w[i] = (const float*)d_in[4 + i];
    const float* wout = (const float*)d_in[16];
    float* out = (float*)d_out;

    void *pPhi, *pPlo, *pAhi, *pAlo, *pWhi, *pWlo, *pOhi, *pOlo, *pHhi, *pHlo;
    cudaGetSymbolAddress(&pPhi, g_Phi);
    cudaGetSymbolAddress(&pPlo, g_Plo);
    cudaGetSymbolAddress(&pAhi, g_Ahi);
    cudaGetSymbolAddress(&pAlo, g_Alo);
    cudaGetSymbolAddress(&pWhi, g_Whi);
    cudaGetSymbolAddress(&pWlo, g_Wlo);
    cudaGetSymbolAddress(&pOhi, g_Ohi);
    cudaGetSymbolAddress(&pOlo, g_Olo);
    cudaGetSymbolAddress(&pHhi, g_Hhi);
    cudaGetSymbolAddress(&pHlo, g_Hlo);

    // 1. repack + split weights; split q, W_out; pack masks
    repack_split_kernel<<<(Dd * NCOL + 255) / 256, 256>>>(wp);
    conv_split_kernel<<<(ROWSM * Dd + 255) / 256, 256>>>(
        q, (__nv_bfloat16*)pAhi, (__nv_bfloat16*)pAlo, ROWSM * Dd);
    conv_split_kernel<<<(Dd * Ee + 255) / 256, 256>>>(
        wout, (__nv_bfloat16*)pOhi, (__nv_bfloat16*)pOlo, Dd * Ee);
    mask_pack_kernel<<<(Bb * 4 * NQq * 8) / 256, 256>>>(attM, grpM, sdM);

    // 2. fused projection GEMM -> bf16 hi/lo planes
    mma_gemm_kernel<<<dim3(NCOL / 64, ROWSM / 64), 128>>>(
        (const __nv_bfloat16*)pAhi, (const __nv_bfloat16*)pAlo,
        (const __nv_bfloat16*)pWhi, (const __nv_bfloat16*)pWlo,
        nullptr, (__nv_bfloat16*)pPhi, (__nv_bfloat16*)pPlo,
        ROWSM, NCOL, Dd, 1);

    // 3. tensor-core fused masked 4-branch attention
    cudaFuncSetAttribute(attn_mma_kernel,
                         cudaFuncAttributeMaxDynamicSharedMemorySize, ATTN_SMEM);
    attn_mma_kernel<<<dim3(4, 128), 128, ATTN_SMEM>>>();

    // 4. output GEMM -> fp32 out
    mma_gemm_kernel<<<dim3(Ee / 64, ROWSM / 64), 128>>>(
        (const __nv_bfloat16*)pHhi, (const __nv_bfloat16*)pHlo,
        (const __nv_bfloat16*)pOhi, (const __nv_bfloat16*)pOlo,
        out, nullptr, nullptr, ROWSM, Ee, Dd, 0);
}

// round 6
// speedup vs baseline: 2.5643x; 1.3025x over previous
#include <cuda_runtime.h>
#include <cuda_bf16.h>
#include <cstdint>

#define Hh   8
#define Bb   16
#define Gg   512
#define NQq  512
#define Dd   512
#define KDd  64
#define Ee   512
#define NCOL 6144           /* 12 * 512 */
#define ROWSM 8192          /* B * NQ   */
#define NORMS 0.125f

typedef unsigned long long u64;

// ---------------- mma.sync / ldmatrix / cp.async helpers -------------------
__device__ __forceinline__ void ldsm4(uint32_t* d, uint32_t addr) {
    asm volatile("ldmatrix.sync.aligned.m8n8.x4.shared.b16 {%0,%1,%2,%3}, [%4];"
                 : "=r"(d[0]), "=r"(d[1]), "=r"(d[2]), "=r"(d[3]) : "r"(addr));
}
__device__ __forceinline__ void ldsm4t(uint32_t* d, uint32_t addr) {
    asm volatile("ldmatrix.sync.aligned.m8n8.x4.trans.shared.b16 {%0,%1,%2,%3}, [%4];"
                 : "=r"(d[0]), "=r"(d[1]), "=r"(d[2]), "=r"(d[3]) : "r"(addr));
}
__device__ __forceinline__ void mma_bf16(float* c, const uint32_t* a,
                                         uint32_t b0, uint32_t b1) {
    asm volatile(
        "mma.sync.aligned.m16n8k16.row.col.f32.bf16.bf16.f32 "
        "{%0,%1,%2,%3}, {%4,%5,%6,%7}, {%8,%9}, {%0,%1,%2,%3};"
        : "+f"(c[0]), "+f"(c[1]), "+f"(c[2]), "+f"(c[3])
        : "r"(a[0]), "r"(a[1]), "r"(a[2]), "r"(a[3]), "r"(b0), "r"(b1));
}
__device__ __forceinline__ void cpa16(uint32_t dst, const void* src) {
    asm volatile("cp.async.cg.shared.global [%0], [%1], 16;"
                 :: "r"(dst), "l"(src));
}
__device__ __forceinline__ void cpa_commit() {
    asm volatile("cp.async.commit_group;" ::: "memory");
}
__device__ __forceinline__ void cpa_wait1() {
    asm volatile("cp.async.wait_group 1;" ::: "memory");
}
// pack two fp32 as bf16x2 (v0 low, v1 high), plus residual plane
__device__ __forceinline__ void split_pair(float v0, float v1,
                                           uint32_t& hi, uint32_t& lo) {
    uint32_t h;
    asm("cvt.rn.bf16x2.f32 %0, %1, %2;" : "=r"(h) : "f"(v1), "f"(v0));
    float f0 = __uint_as_float(h << 16);
    float f1 = __uint_as_float(h & 0xFFFF0000u);
    uint32_t l;
    asm("cvt.rn.bf16x2.f32 %0, %1, %2;" : "=r"(l) : "f"(v1 - f1), "f"(v0 - f0));
    hi = h; lo = l;
}

// ---------------- device scratch (static: allocation-guard safe) ----------
__device__ __nv_bfloat16 g_Phi[(size_t)ROWSM * NCOL];  // projections hi
__device__ __nv_bfloat16 g_Plo[(size_t)ROWSM * NCOL];  // projections lo
__device__ u64 g_mask[(size_t)Bb * 4 * NQq * 8];       // packed masks (64 keys/word)

__device__ __nv_bfloat16 g_Ahi[(size_t)ROWSM * Dd];    // q split
__device__ __nv_bfloat16 g_Alo[(size_t)ROWSM * Dd];
__device__ __nv_bfloat16 g_Whi[(size_t)Dd * NCOL];     // fused weights split
__device__ __nv_bfloat16 g_Wlo[(size_t)Dd * NCOL];
__device__ __nv_bfloat16 g_Ohi[Dd * Ee];               // W_out split
__device__ __nv_bfloat16 g_Olo[Dd * Ee];
__device__ __nv_bfloat16 g_Hhi[(size_t)ROWSM * Dd];    // heads split (B,NQ,H,VD)
__device__ __nv_bfloat16 g_Hlo[(size_t)ROWSM * Dd];

struct WPtrs { const float* w[12]; };

// ---------------- weight repack + split: 12 x (H,D,64) -> hi/lo [D][6144] --
__global__ void repack_split_kernel(WPtrs wp) {
    int idx = blockIdx.x * blockDim.x + threadIdx.x;
    if (idx >= Dd * NCOL) return;
    int d   = idx / NCOL;
    int col = idx - d * NCOL;
    int w   = col >> 9;
    int hk  = col & 511;
    int h   = hk >> 6;
    int k   = hk & 63;
    float x = wp.w[w][((size_t)h * Dd + d) * KDd + k];
    __nv_bfloat16 hi = __float2bfloat16_rn(x);
    g_Whi[idx] = hi;
    g_Wlo[idx] = __float2bfloat16_rn(x - __bfloat162float(hi));
}

// ---------------- generic fp32 -> bf16 hi/lo split -------------------------
__global__ void conv_split_kernel(const float* __restrict__ src,
                                  __nv_bfloat16* __restrict__ hi,
                                  __nv_bfloat16* __restrict__ lo, int n) {
    int i = blockIdx.x * blockDim.x + threadIdx.x;
    if (i >= n) return;
    float x = src[i];
    __nv_bfloat16 h = __float2bfloat16_rn(x);
    hi[i] = h;
    lo[i] = __float2bfloat16_rn(x - __bfloat162float(h));
}

// ---------------- mask pack (row-major branches 0,2,3) via ballot ---------
// warp per (b, branch, q): 16 ballots of 32 coalesced elements
__global__ void mask_row_kernel(const float* __restrict__ attm,
                                const float* __restrict__ gmk,
                                const float* __restrict__ sd) {
    int widx = blockIdx.x * 8 + (threadIdx.x >> 5);   // 0..24575
    int lane = threadIdx.x & 31;
    int q = widx & 511;
    int t = widx >> 9;          // 0..47
    int br = t % 3;             // 0->sd(c0), 1->attm(c2), 2->gmk(c3)
    int b  = t / 3;
    const float* row;
    int c;
    if (br == 0)      { row = sd   + ((size_t)b * 512 + q) * 512; c = 0; }
    else if (br == 1) { row = attm + ((size_t)b * 512 + q) * 512; c = 2; }
    else              { row = gmk  + ((size_t)b * 512 + q) * 512; c = 3; }
#pragma unroll
    for (int tile = 0; tile < 8; tile++) {
        uint32_t b0 = __ballot_sync(0xffffffffu, row[tile * 64 + lane] != 0.0f);
        uint32_t b1 = __ballot_sync(0xffffffffu, row[tile * 64 + 32 + lane] != 0.0f);
        if (lane == 0)
            g_mask[(((size_t)b * 4 + c) * 512 + q) * 8 + tile] =
                (u64)b0 | ((u64)b1 << 32);
    }
}

// ---------------- mask pack (transposed branch 1) via smem + ballot -------
// block per (gtile, qtile, b): load 64x64 coalesced, ballot columns
__global__ void mask_t_kernel(const float* __restrict__ attm) {
    __shared__ float t[64 * 65];
    int gt = blockIdx.x;        // 0..7 (g tile)
    int qt = blockIdx.y;        // 0..7 (q tile)
    int b  = blockIdx.z;
    int tid = threadIdx.x;      // 256
    const float* src = attm + ((size_t)b * 512 + gt * 64) * 512 + qt * 64;
#pragma unroll
    for (int it = 0; it < 16; it++) {
        int idx = tid + it * 256;
        int r = idx >> 6, cc = idx & 63;
        t[r * 65 + cc] = src[(size_t)r * 512 + cc];
    }
    __syncthreads();
    int w = tid >> 5, lane = tid & 31;
#pragma unroll
    for (int qq = 0; qq < 8; qq++) {
        int q = w * 8 + qq;
        uint32_t b0 = __ballot_sync(0xffffffffu, t[lane * 65 + q] != 0.0f);
        uint32_t b1 = __ballot_sync(0xffffffffu, t[(lane + 32) * 65 + q] != 0.0f);
        if (lane == 0)
            g_mask[(((size_t)b * 4 + 1) * 512 + qt * 64 + q) * 8 + gt] =
                (u64)b0 | ((u64)b1 << 32);
    }
}

// ---------------- bf16x3 pipelined MMA GEMM: C[M,N] = A[M,K]*B[K,N] -------
// 128x128x32 block tile, 256 threads (2m x 4n warps, warp tile 64x32),
// 3-stage cp.async pipeline. bf16out: write Chi/Clo planes else fp32 C.
#define GSTAGE_ELEMS 18944          /* 2*128*40 + 2*32*136 */
#define GSMEM_BYTES  (3 * GSTAGE_ELEMS * 2)

__global__ __launch_bounds__(256) void mma_gemm2_kernel(
    const __nv_bfloat16* __restrict__ Ahi, const __nv_bfloat16* __restrict__ Alo,
    const __nv_bfloat16* __restrict__ Bhi, const __nv_bfloat16* __restrict__ Blo,
    float* __restrict__ C,
    __nv_bfloat16* __restrict__ Chi, __nv_bfloat16* __restrict__ Clo,
    int M, int N, int K, int bf16out) {
    extern __shared__ __nv_bfloat16 gsm[];
    uint32_t sb = (uint32_t)__cvta_generic_to_shared(gsm);

    int tid  = threadIdx.x;
    int lane = tid & 31;
    int wid  = tid >> 5;
    int wm   = wid & 1;          // 2 m-warps * 64
    int wn   = wid >> 1;         // 4 n-warps * 32

    int m0 = blockIdx.y * 128;
    int n0 = blockIdx.x * 128;

    const __nv_bfloat16* Ag[2] = { Ahi, Alo };
    const __nv_bfloat16* Bg[2] = { Bhi, Blo };

    float acc[4][4][4];
#pragma unroll
    for (int mf = 0; mf < 4; mf++)
#pragma unroll
        for (int nf = 0; nf < 4; nf++)
#pragma unroll
            for (int e = 0; e < 4; e++) acc[mf][nf][e] = 0.f;

    // loader indices
    int arow = tid >> 1;                 // 0..127 (x2 chunks)
    int achk = tid & 1;                  // chunks 0..3 via +2
    int brow = tid >> 3;                 // 0..31
    int bchk = tid & 7;                  // 0..7 (16 chunks via +8)

    int steps = K >> 5;                  // K/32

    // stage issuer
    auto issue = [&](int st, int k0) {
        uint32_t stg = sb + (uint32_t)(st * GSTAGE_ELEMS) * 2;
#pragma unroll
        for (int p = 0; p < 2; p++) {
#pragma unroll
            for (int cc = 0; cc < 2; cc++) {
                int chunk = achk + cc * 2;
                cpa16(stg + (uint32_t)(p * 5120 + arow * 40 + chunk * 8) * 2,
                      Ag[p] + (size_t)(m0 + arow) * K + k0 + chunk * 8);
            }
#pragma unroll
            for (int cc = 0; cc < 2; cc++) {
                int chunk = bchk + cc * 8;
                cpa16(stg + (uint32_t)(10240 + p * 4352 + brow * 136 + chunk * 8) * 2,
                      Bg[p] + (size_t)(k0 + brow) * N + n0 + chunk * 8);
            }
        }
    };

    issue(0, 0); cpa_commit();
    issue(1, 32); cpa_commit();

    for (int i = 0; i < steps; i++) {
        cpa_wait1();
        __syncthreads();
        uint32_t stg = sb + (uint32_t)((i % 3) * GSTAGE_ELEMS) * 2;

#pragma unroll
        for (int ks = 0; ks < 2; ks++) {
            uint32_t a[2][4][4];
#pragma unroll
            for (int p = 0; p < 2; p++)
#pragma unroll
                for (int mf = 0; mf < 4; mf++) {
                    uint32_t off = (uint32_t)(p * 5120 +
                        (wm * 64 + mf * 16 + (lane & 15)) * 40 +
                        ks * 16 + (lane >> 4) * 8) * 2;
                    ldsm4(a[p][mf], stg + off);
                }
#pragma unroll
            for (int pr = 0; pr < 2; pr++) {
                uint32_t bh[4], bl[4];
                uint32_t offh = (uint32_t)(10240 +
                    (ks * 16 + (lane & 15)) * 136 +
                    wn * 32 + pr * 16 + (lane >> 4) * 8) * 2;
                ldsm4t(bh, stg + offh);
                ldsm4t(bl, stg + offh + (uint32_t)4352 * 2);
#pragma unroll
                for (int mf = 0; mf < 4; mf++) {
#pragma unroll
                    for (int hh = 0; hh < 2; hh++) {
                        int nf = 2 * pr + hh;
                        mma_bf16(acc[mf][nf], a[0][mf], bh[2 * hh], bh[2 * hh + 1]);
                        mma_bf16(acc[mf][nf], a[0][mf], bl[2 * hh], bl[2 * hh + 1]);
                        mma_bf16(acc[mf][nf], a[1][mf], bh[2 * hh], bh[2 * hh + 1]);
                    }
                }
            }
        }
        if (i + 2 < steps) issue((i + 2) % 3, (i + 2) * 32);
        cpa_commit();
    }

    // epilogue
#pragma unroll
    for (int mf = 0; mf < 4; mf++) {
        int gm = m0 + wm * 64 + mf * 16 + (lane >> 2);
#pragma unroll
        for (int nf = 0; nf < 4; nf++) {
            int gn = n0 + wn * 32 + nf * 8 + (lane & 3) * 2;
            if (bf16out) {
                uint32_t h2, l2;
                split_pair(acc[mf][nf][0], acc[mf][nf][1], h2, l2);
                *(uint32_t*)(Chi + (size_t)gm * N + gn) = h2;
                *(uint32_t*)(Clo + (size_t)gm * N + gn) = l2;
                split_pair(acc[mf][nf][2], acc[mf][nf][3], h2, l2);
                *(uint32_t*)(Chi + (size_t)(gm + 8) * N + gn) = h2;
                *(uint32_t*)(Clo + (size_t)(gm + 8) * N + gn) = l2;
            } else {
                *(float2*)(C + (size_t)gm * N + gn) =
                    make_float2(acc[mf][nf][0], acc[mf][nf][1]);
                *(float2*)(C + (size_t)(gm + 8) * N + gn) =
                    make_float2(acc[mf][nf][2], acc[mf][nf][3]);
            }
        }
    }
}

// ---------------- tensor-core fused attention (unchanged from R5) ----------
#define QSTR 72
#define ATTN_SMEM ((128 * QSTR * 2 + 64 * QSTR * 4) * 2)   /* 73728 B */

__global__ __launch_bounds__(128) void attn_mma_kernel() {
    extern __shared__ __nv_bfloat16 sm[];
    __nv_bfloat16* Qhi = sm;
    __nv_bfloat16* Qlo = Qhi + 128 * QSTR;
    __nv_bfloat16* Khi = Qlo + 128 * QSTR;
    __nv_bfloat16* Klo = Khi + 64 * QSTR;
    __nv_bfloat16* Vhi = Klo + 64 * QSTR;
    __nv_bfloat16* Vlo = Vhi + 64 * QSTR;

    int qt = blockIdx.x;
    int hb = blockIdx.y;
    int h  = hb >> 4;
    int b  = hb & 15;
    int tid  = threadIdx.x;
    int lane = tid & 31;
    int wq   = tid >> 5;

    uint32_t qhi_b = (uint32_t)__cvta_generic_to_shared(Qhi);
    uint32_t qlo_b = (uint32_t)__cvta_generic_to_shared(Qlo);
    uint32_t khi_b = (uint32_t)__cvta_generic_to_shared(Khi);
    uint32_t klo_b = (uint32_t)__cvta_generic_to_shared(Klo);
    uint32_t vhi_b = (uint32_t)__cvta_generic_to_shared(Vhi);
    uint32_t vlo_b = (uint32_t)__cvta_generic_to_shared(Vlo);

    float o[2][8][4];
    float mrow[2][2], den[2][2];
#pragma unroll
    for (int mf = 0; mf < 2; mf++) {
#pragma unroll
        for (int vf = 0; vf < 8; vf++)
#pragma unroll
            for (int e = 0; e < 4; e++) o[mf][vf][e] = 0.f;
        mrow[mf][0] = mrow[mf][1] = -1e30f;
        den[mf][0] = den[mf][1] = 0.f;
    }

    int ldr = tid >> 3;
    int c8  = tid & 7;

    for (int c = 0; c < 4; c++) {
        __syncthreads();
        {
            const __nv_bfloat16* Qg = g_Phi + (size_t)(b * 512 + qt * 128) * NCOL
                                      + (3 * c) * 512 + h * 64;
            const __nv_bfloat16* Qg2 = g_Plo + (size_t)(b * 512 + qt * 128) * NCOL
                                      + (3 * c) * 512 + h * 64;
#pragma unroll
            for (int it = 0; it < 8; it++) {
                int row = ldr + it * 16;
                *(uint4*)(Qhi + row * QSTR + c8 * 8) =
                    *(const uint4*)(Qg + (size_t)row * NCOL + c8 * 8);
                *(uint4*)(Qlo + row * QSTR + c8 * 8) =
                    *(const uint4*)(Qg2 + (size_t)row * NCOL + c8 * 8);
            }
        }
        size_t mrow_base = (((size_t)b * 4 + c) * 512 + qt * 128) * 8;

        for (int g0t = 0; g0t < 8; g0t++) {
            __syncthreads();
            {
                size_t gbase = (size_t)(b * 512 + g0t * 64) * NCOL + h * 64 + c8 * 8;
                const __nv_bfloat16* KgH = g_Phi + gbase + (3 * c + 1) * 512;
                const __nv_bfloat16* KgL = g_Plo + gbase + (3 * c + 1) * 512;
                const __nv_bfloat16* VgH = g_Phi + gbase + (3 * c + 2) * 512;
                const __nv_bfloat16* VgL = g_Plo + gbase + (3 * c + 2) * 512;
#pragma unroll
                for (int it = 0; it < 4; it++) {
                    int row = ldr + it * 16;
                    *(uint4*)(Khi + row * QSTR + c8 * 8) = *(const uint4*)(KgH + (size_t)row * NCOL);
                    *(uint4*)(Klo + row * QSTR + c8 * 8) = *(const uint4*)(KgL + (size_t)row * NCOL);
                    *(uint4*)(Vhi + row * QSTR + c8 * 8) = *(const uint4*)(VgH + (size_t)row * NCOL);
                    *(uint4*)(Vlo + row * QSTR + c8 * 8) = *(const uint4*)(VgL + (size_t)row * NCOL);
                }
            }
            __syncthreads();

            u64 mw[2][2];
#pragma unroll
            for (int mf = 0; mf < 2; mf++)
#pragma unroll
                for (int hf = 0; hf < 2; hf++) {
                    int ql = wq * 32 + mf * 16 + (lane >> 2) + 8 * hf;
                    mw[mf][hf] = g_mask[mrow_base + (size_t)ql * 8 + g0t];
                }

            float s[2][8][4];
#pragma unroll
            for (int mf = 0; mf < 2; mf++)
#pragma unroll
                for (int nf = 0; nf < 8; nf++)
#pragma unroll
                    for (int e = 0; e < 4; e++) s[mf][nf][e] = 0.f;

#pragma unroll
            for (int ks = 0; ks < 4; ks++) {
                uint32_t ah[2][4], al[2][4];
#pragma unroll
                for (int mf = 0; mf < 2; mf++) {
                    uint32_t off = ((wq * 32 + mf * 16 + (lane & 15)) * QSTR +
                                    ks * 16 + (lane >> 4) * 8) * 2;
                    ldsm4(ah[mf], qhi_b + off);
                    ldsm4(al[mf], qlo_b + off);
                }
#pragma unroll
                for (int pr = 0; pr < 4; pr++) {
                    uint32_t off = ((pr * 16 + (lane & 7) + ((lane >> 4) & 1) * 8) * QSTR +
                                    ks * 16 + ((lane >> 3) & 1) * 8) * 2;
                    uint32_t kh[4], kl[4];
                    ldsm4(kh, khi_b + off);
                    ldsm4(kl, klo_b + off);
#pragma unroll
                    for (int mf = 0; mf < 2; mf++) {
                        mma_bf16(s[mf][2 * pr],     ah[mf], kh[0], kh[1]);
                        mma_bf16(s[mf][2 * pr],     ah[mf], kl[0], kl[1]);
                        mma_bf16(s[mf][2 * pr],     al[mf], kh[0], kh[1]);
                        mma_bf16(s[mf][2 * pr + 1], ah[mf], kh[2], kh[3]);
                        mma_bf16(s[mf][2 * pr + 1], ah[mf], kl[2], kl[3]);
                        mma_bf16(s[mf][2 * pr + 1], al[mf], kh[2], kh[3]);
                    }
                }
            }

#pragma unroll
            for (int mf = 0; mf < 2; mf++)
#pragma unroll
                for (int hf = 0; hf < 2; hf++) {
                    int i0 = 2 * hf;
                    u64 w = mw[mf][hf];
                    int sb2 = 2 * (lane & 3);
                    float rm = -1e30f;
#pragma unroll
                    for (int nf = 0; nf < 8; nf++) {
                        uint32_t bits = (uint32_t)(w >> (nf * 8 + sb2)) & 3u;
                        float v0 = (bits & 1u) ? s[mf][nf][i0] * NORMS : -1e30f;
                        float v1 = (bits & 2u) ? s[mf][nf][i0 + 1] * NORMS : -1e30f;
                        s[mf][nf][i0]     = v0;
                        s[mf][nf][i0 + 1] = v1;
                        rm = fmaxf(rm, fmaxf(v0, v1));
                    }
                    rm = fmaxf(rm, __shfl_xor_sync(0xffffffffu, rm, 1));
                    rm = fmaxf(rm, __shfl_xor_sync(0xffffffffu, rm, 2));
                    float mo = mrow[mf][hf];
                    float mn = fmaxf(mo, rm);
                    float sc = __expf(mo - mn);
                    float rs = 0.f;
#pragma unroll
                    for (int nf = 0; nf < 8; nf++) {
                        float v0 = s[mf][nf][i0];
                        float v1 = s[mf][nf][i0 + 1];
                        float p0 = (v0 > -1e29f) ? __expf(v0 - mn) : 0.f;
                        float p1 = (v1 > -1e29f) ? __expf(v1 - mn) : 0.f;
                        s[mf][nf][i0]     = p0;
                        s[mf][nf][i0 + 1] = p1;
                        rs += p0 + p1;
                    }
                    rs += __shfl_xor_sync(0xffffffffu, rs, 1);
                    rs += __shfl_xor_sync(0xffffffffu, rs, 2);
                    den[mf][hf] = den[mf][hf] * sc + rs;
                    mrow[mf][hf] = mn;
#pragma unroll
                    for (int vf = 0; vf < 8; vf++) {
                        o[mf][vf][i0]     *= sc;
                        o[mf][vf][i0 + 1] *= sc;
                    }
                }

#pragma unroll
            for (int ks = 0; ks < 4; ks++) {
                uint32_t ph[2][4], pl[2][4];
#pragma unroll
                for (int mf = 0; mf < 2; mf++) {
                    split_pair(s[mf][2 * ks][0],     s[mf][2 * ks][1],     ph[mf][0], pl[mf][0]);
                    split_pair(s[mf][2 * ks][2],     s[mf][2 * ks][3],     ph[mf][1], pl[mf][1]);
                    split_pair(s[mf][2 * ks + 1][0], s[mf][2 * ks + 1][1], ph[mf][2], pl[mf][2]);
                    split_pair(s[mf][2 * ks + 1][2], s[mf][2 * ks + 1][3], ph[mf][3], pl[mf][3]);
                }
#pragma unroll
                for (int pr = 0; pr < 4; pr++) {
                    uint32_t off = ((ks * 16 + (lane & 15)) * QSTR +
                                    pr * 16 + (lane >> 4) * 8) * 2;
                    uint32_t vh[4], vl[4];
                    ldsm4t(vh, vhi_b + off);
                    ldsm4t(vl, vlo_b + off);
#pragma unroll
                    for (int mf = 0; mf < 2; mf++) {
                        mma_bf16(o[mf][2 * pr],     ph[mf], vh[0], vh[1]);
                        mma_bf16(o[mf][2 * pr],     ph[mf], vl[0], vl[1]);
                        mma_bf16(o[mf][2 * pr],     pl[mf], vh[0], vh[1]);
                        mma_bf16(o[mf][2 * pr + 1], ph[mf], vh[2], vh[3]);
                        mma_bf16(o[mf][2 * pr + 1], ph[mf], vl[2], vl[3]);
                        mma_bf16(o[mf][2 * pr + 1], pl[mf], vh[2], vh[3]);
                    }
                }
            }
        }
    }

#pragma unroll
    for (int mf = 0; mf < 2; mf++)
#pragma unroll
        for (int hf = 0; hf < 2; hf++) {
            int ql = wq * 32 + mf * 16 + (lane >> 2) + 8 * hf;
            float dv = den[mf][hf];
            float inv = (dv > 0.f) ? 1.f / dv : 0.f;
            size_t base = ((size_t)(b * 512 + qt * 128 + ql)) * 512 + h * 64;
#pragma unroll
            for (int vf = 0; vf < 8; vf++) {
                float v0 = o[mf][vf][2 * hf] * inv;
                float v1 = o[mf][vf][2 * hf + 1] * inv;
                uint32_t h2, l2;
                split_pair(v0, v1, h2, l2);
                int col = vf * 8 + 2 * (lane & 3);
                *(uint32_t*)(g_Hhi + base + col) = h2;
                *(uint32_t*)(g_Hlo + base + col) = l2;
            }
        }
}

// ---------------- launch ---------------------------------------------------
extern "C" void kernel_launch(void* const* d_in, const int* in_sizes, int n_in,
                              void* d_out, int out_size) {
    const float* q    = (const float*)d_in[0];
    const float* attM = (const float*)d_in[1];
    const float* grpM = (const float*)d_in[2];
    const float* sdM  = (const float*)d_in[3];
    WPtrs wp;
    for (int i = 0; i < 12; i++) wp.w[i] = (const float*)d_in[4 + i];
    const float* wout = (const float*)d_in[16];
    float* out = (float*)d_out;

    void *pPhi, *pPlo, *pAhi, *pAlo, *pWhi, *pWlo, *pOhi, *pOlo, *pHhi, *pHlo;
    cudaGetSymbolAddress(&pPhi, g_Phi);
    cudaGetSymbolAddress(&pPlo, g_Plo);
    cudaGetSymbolAddress(&pAhi, g_Ahi);
    cudaGetSymbolAddress(&pAlo, g_Alo);
    cudaGetSymbolAddress(&pWhi, g_Whi);
    cudaGetSymbolAddress(&pWlo, g_Wlo);
    cudaGetSymbolAddress(&pOhi, g_Ohi);
    cudaGetSymbolAddress(&pOlo, g_Olo);
    cudaGetSymbolAddress(&pHhi, g_Hhi);
    cudaGetSymbolAddress(&pHlo, g_Hlo);

    // 1. repack + split weights; split q, W_out; pack masks
    repack_split_kernel<<<(Dd * NCOL + 255) / 256, 256>>>(wp);
    conv_split_kernel<<<(ROWSM * Dd + 255) / 256, 256>>>(
        q, (__nv_bfloat16*)pAhi, (__nv_bfloat16*)pAlo, ROWSM * Dd);
    conv_split_kernel<<<(Dd * Ee + 255) / 256, 256>>>(
        wout, (__nv_bfloat16*)pOhi, (__nv_bfloat16*)pOlo, Dd * Ee);
    mask_row_kernel<<<3072, 256>>>(attM, grpM, sdM);
    mask_t_kernel<<<dim3(8, 8, 16), 256>>>(attM);

    // 2. fused projection GEMM -> bf16 hi/lo planes (pipelined)
    cudaFuncSetAttribute(mma_gemm2_kernel,
                         cudaFuncAttributeMaxDynamicSharedMemorySize, GSMEM_BYTES);
    mma_gemm2_kernel<<<dim3(NCOL / 128, ROWSM / 128), 256, GSMEM_BYTES>>>(
        (const __nv_bfloat16*)pAhi, (const __nv_bfloat16*)pAlo,
        (const __nv_bfloat16*)pWhi, (const __nv_bfloat16*)pWlo,
        nullptr, (__nv_bfloat16*)pPhi, (__nv_bfloat16*)pPlo,
        ROWSM, NCOL, Dd, 1);

    // 3. tensor-core fused masked 4-branch attention
    cudaFuncSetAttribute(attn_mma_kernel,
                         cudaFuncAttributeMaxDynamicSharedMemorySize, ATTN_SMEM);
    attn_mma_kernel<<<dim3(4, 128), 128, ATTN_SMEM>>>();

    // 4. output GEMM -> fp32 out
    mma_gemm2_kernel<<<dim3(Ee / 128, ROWSM / 128), 256, GSMEM_BYTES>>>(
        (const __nv_bfloat16*)pHhi, (const __nv_bfloat16*)pHlo,
        (const __nv_bfloat16*)pOhi, (const __nv_bfloat16*)pOlo,
        out, nullptr, nullptr, ROWSM, Ee, Dd, 0);
}